// round 5
// baseline (speedup 1.0000x reference)
#include <cuda_runtime.h>

#define BATCH  16
#define NPAT   1024
#define EMB    128
#define HEADS  8
#define ROWS_TOT (BATCH*NPAT)      /* 16384 */
#define INNERD   (EMB*HEADS)       /* 1024  */

// ---------------- scratch (static device allocations; allowed) ----------------
__device__ float g_xn[ROWS_TOT*EMB];                 //  8 MB  layernormed x
__device__ float g_q [BATCH*HEADS*NPAT*EMB];         // 64 MB  [bh][n][d]
__device__ float g_k [BATCH*HEADS*NPAT*EMB];         // 64 MB
__device__ float g_v [BATCH*HEADS*NPAT*EMB];         // 64 MB
__device__ float g_ao[ROWS_TOT*INNERD];              // 64 MB  [b*n][h*128+d]

// =============================== LayerNorm ===============================
__global__ void ln_kernel(const float* __restrict__ x,
                          const float* __restrict__ w,
                          const float* __restrict__ b) {
    int row = blockIdx.x, t = threadIdx.x;
    float v = x[row*EMB + t];
    float s = v;
    #pragma unroll
    for (int o = 16; o; o >>= 1) s += __shfl_xor_sync(0xffffffffu, s, o);
    __shared__ float r1[4], r2[4];
    if ((t & 31) == 0) r1[t >> 5] = s;
    __syncthreads();
    float mean = (r1[0] + r1[1] + r1[2] + r1[3]) * (1.0f/EMB);
    float d = v - mean;
    float q = d * d;
    #pragma unroll
    for (int o = 16; o; o >>= 1) q += __shfl_xor_sync(0xffffffffu, q, o);
    if ((t & 31) == 0) r2[t >> 5] = q;
    __syncthreads();
    float var = (r2[0] + r2[1] + r2[2] + r2[3]) * (1.0f/EMB);
    g_xn[row*EMB + t] = d * rsqrtf(var + 1e-5f) * w[t] + b[t];
}

// =============================== QKV GEMM ===============================
// C[16384,3072] = xn[16384,128] @ wqkv[128,3072], scattered into q/k/v head layout.
// 64x64 tile, 256 threads, 4x4 microtile, full K=128 in smem (k-major).
__global__ void __launch_bounds__(256) qkv_kernel(const float* __restrict__ wqkv) {
    extern __shared__ float sm[];
    float* Ast = sm;           // [128][64]  (xn transposed)
    float* Bs  = sm + 8192;    // [128][64]  (wqkv slice, already k-major)
    int t = threadIdx.x;
    int rowbase = blockIdx.y * 64;
    int colbase = blockIdx.x * 64;

    #pragma unroll
    for (int l = 0; l < 8; l++) {                 // transpose-load A
        int e = l*256 + t, i = e & 63, k4 = e >> 6;
        float4 g = *(const float4*)&g_xn[(rowbase+i)*EMB + k4*4];
        Ast[(k4*4+0)*64 + i] = g.x;  Ast[(k4*4+1)*64 + i] = g.y;
        Ast[(k4*4+2)*64 + i] = g.z;  Ast[(k4*4+3)*64 + i] = g.w;
    }
    #pragma unroll
    for (int l = 0; l < 8; l++) {                 // direct-load B
        int e = l*256 + t, k = e >> 4, j4 = e & 15;
        *(float4*)&Bs[k*64 + j4*4] =
            *(const float4*)&wqkv[k*3072 + colbase + j4*4];
    }
    __syncthreads();

    int ty = t >> 4, tx = t & 15;
    float acc[4][4] = {};
    #pragma unroll 8
    for (int k = 0; k < 128; k++) {
        float4 a = *(float4*)&Ast[k*64 + ty*4];
        float4 bb = *(float4*)&Bs [k*64 + tx*4];
        float av[4] = {a.x, a.y, a.z, a.w};
        float bv[4] = {bb.x, bb.y, bb.z, bb.w};
        #pragma unroll
        for (int i = 0; i < 4; i++)
            #pragma unroll
            for (int jj = 0; jj < 4; jj++) acc[i][jj] += av[i] * bv[jj];
    }

    int section = colbase >> 10;          // 0:q 1:k 2:v (64-col tile never straddles)
    int h     = (colbase & 1023) >> 7;
    int dbase = colbase & 127;
    float* dst = (section == 0) ? g_q : ((section == 1) ? g_k : g_v);
    #pragma unroll
    for (int i = 0; i < 4; i++) {
        int row = rowbase + ty*4 + i;
        int bb = row >> 10, n = row & 1023;
        float4 o = make_float4(acc[i][0], acc[i][1], acc[i][2], acc[i][3]);
        *(float4*)&dst[((bb*HEADS + h)*NPAT + n)*EMB + dbase + tx*4] = o;
    }
}

// ====================== Flash attention (per 64-query tile) ======================
// grid (16 qtiles, 128 bh), 256 threads. Online softmax, diag masked to -FLT_MAX.
__global__ void __launch_bounds__(256) attn_kernel(const float* __restrict__ scale) {
    extern __shared__ float sm[];
    float* Qst = sm;            // [128][64]  Q^T * scale
    float* Kst = sm + 8192;     // [128][64]  K^T
    float* Vs  = sm + 16384;    // [64][128]  V
    float* Pst = sm + 24576;    // [64][65]   P^T (padded stride 65)
    int t = threadIdx.x;
    int bh = blockIdx.y;
    int qbase = blockIdx.x * 64;
    const float* Qg  = g_q + (bh*NPAT + qbase)*EMB;
    const float* Kg0 = g_k + bh*NPAT*EMB;
    const float* Vg0 = g_v + bh*NPAT*EMB;
    float sc = scale[bh & (HEADS-1)];

    #pragma unroll
    for (int l = 0; l < 8; l++) {                 // Q transpose + scale fold
        int e = l*256 + t, i = e & 63, k4 = e >> 6;
        float4 g = *(const float4*)&Qg[i*EMB + k4*4];
        Qst[(k4*4+0)*64 + i] = g.x*sc;  Qst[(k4*4+1)*64 + i] = g.y*sc;
        Qst[(k4*4+2)*64 + i] = g.z*sc;  Qst[(k4*4+3)*64 + i] = g.w*sc;
    }

    int ty = t >> 4, tx = t & 15;
    float m[4], lsum[4], acc[4][8];
    #pragma unroll
    for (int i = 0; i < 4; i++) {
        m[i] = -3.402823466e38f; lsum[i] = 0.f;
        #pragma unroll
        for (int c = 0; c < 8; c++) acc[i][c] = 0.f;
    }

    for (int j = 0; j < 16; j++) {
        __syncthreads();                          // prev iter smem reads done
        const float* Kg = Kg0 + j*64*EMB;
        const float* Vg = Vg0 + j*64*EMB;
        #pragma unroll
        for (int l = 0; l < 8; l++) {             // K transpose (conflict-free STS)
            int e = l*256 + t, i = e & 63, k4 = e >> 6;
            float4 g = *(const float4*)&Kg[i*EMB + k4*4];
            Kst[(k4*4+0)*64 + i] = g.x;  Kst[(k4*4+1)*64 + i] = g.y;
            Kst[(k4*4+2)*64 + i] = g.z;  Kst[(k4*4+3)*64 + i] = g.w;
        }
        #pragma unroll
        for (int l = 0; l < 8; l++) {             // V direct copy
            int e = l*256 + t, r = e >> 5, c4 = e & 31;
            *(float4*)&Vs[r*EMB + c4*4] = *(const float4*)&Vg[r*EMB + c4*4];
        }
        __syncthreads();

        // ---- S = (Q*sc) K^T  (64x64, 4x4 per thread) ----
        float s[4][4] = {};
        #pragma unroll 8
        for (int k = 0; k < 128; k++) {
            float4 a = *(float4*)&Qst[k*64 + ty*4];
            float4 b = *(float4*)&Kst[k*64 + tx*4];
            float av[4] = {a.x, a.y, a.z, a.w};
            float bv[4] = {b.x, b.y, b.z, b.w};
            #pragma unroll
            for (int i = 0; i < 4; i++)
                #pragma unroll
                for (int jj = 0; jj < 4; jj++) s[i][jj] += av[i] * bv[jj];
        }

        // ---- diagonal mask (only the matching tile can contain it) ----
        if (j == (int)blockIdx.x) {
            int row0 = qbase + ty*4, col0 = j*64 + tx*4;
            #pragma unroll
            for (int i = 0; i < 4; i++)
                #pragma unroll
                for (int jj = 0; jj < 4; jj++)
                    if (row0 + i == col0 + jj) s[i][jj] = -3.402823466e38f;
        }

        // ---- online softmax (row reductions via 16-lane shfl groups) ----
        #pragma unroll
        for (int i = 0; i < 4; i++) {
            float rm = fmaxf(fmaxf(s[i][0], s[i][1]), fmaxf(s[i][2], s[i][3]));
            #pragma unroll
            for (int o = 1; o < 16; o <<= 1)
                rm = fmaxf(rm, __shfl_xor_sync(0xffffffffu, rm, o));
            float mn   = fmaxf(m[i], rm);
            float corr = __expf(m[i] - mn);
            m[i] = mn;
            float rs = 0.f;
            #pragma unroll
            for (int jj = 0; jj < 4; jj++) { s[i][jj] = __expf(s[i][jj] - mn); rs += s[i][jj]; }
            #pragma unroll
            for (int o = 1; o < 16; o <<= 1)
                rs += __shfl_xor_sync(0xffffffffu, rs, o);
            lsum[i] = lsum[i]*corr + rs;
            #pragma unroll
            for (int c = 0; c < 8; c++) acc[i][c] *= corr;
        }

        // ---- stash P^T to smem (stride 65 -> at most 2-way conflicts) ----
        #pragma unroll
        for (int i = 0; i < 4; i++)
            #pragma unroll
            for (int jj = 0; jj < 4; jj++)
                Pst[(tx*4 + jj)*65 + ty*4 + i] = s[i][jj];
        __syncthreads();

        // ---- O += P V  (64x128, 4x8 per thread) ----
        #pragma unroll 8
        for (int k = 0; k < 64; k++) {
            float p[4];
            #pragma unroll
            for (int i = 0; i < 4; i++) p[i] = Pst[k*65 + ty*4 + i];
            float4 v0 = *(float4*)&Vs[k*EMB + tx*8];
            float4 v1 = *(float4*)&Vs[k*EMB + tx*8 + 4];
            float vv[8] = {v0.x, v0.y, v0.z, v0.w, v1.x, v1.y, v1.z, v1.w};
            #pragma unroll
            for (int i = 0; i < 4; i++)
                #pragma unroll
                for (int c = 0; c < 8; c++) acc[i][c] += p[i] * vv[c];
        }
    }

    // ---- epilogue: normalize and write [b][n][h*128+d] ----
    int bb = bh >> 3, h = bh & 7;
    #pragma unroll
    for (int i = 0; i < 4; i++) {
        float inv = 1.0f / lsum[i];
        int n = qbase + ty*4 + i;
        float* op = g_ao + (bb*NPAT + n)*INNERD + h*EMB + tx*8;
        float4 o0 = make_float4(acc[i][0]*inv, acc[i][1]*inv, acc[i][2]*inv, acc[i][3]*inv);
        float4 o1 = make_float4(acc[i][4]*inv, acc[i][5]*inv, acc[i][6]*inv, acc[i][7]*inv);
        *(float4*)&op[0] = o0;
        *(float4*)&op[4] = o1;
    }
}

// =============================== Output projection ===============================
// out[16384,128] = g_ao[16384,1024] @ wp[1024,128] + bias. 64x128 tile, BK=32.
__global__ void __launch_bounds__(256) proj_kernel(const float* __restrict__ wp,
                                                   const float* __restrict__ bias,
                                                   float* __restrict__ out) {
    __shared__ float Ast[32*64];    // A^T chunk
    __shared__ float Bs [32*128];   // W chunk (k-major already)
    int t = threadIdx.x;
    int rowbase = blockIdx.x * 64;
    int ty = t >> 4, tx = t & 15;
    float acc[4][8] = {};

    for (int kb = 0; kb < 1024; kb += 32) {
        __syncthreads();
        #pragma unroll
        for (int l = 0; l < 2; l++) {
            int e = l*256 + t, i = e & 63, k4 = e >> 6;   // k4 in 0..7
            float4 g = *(const float4*)&g_ao[(rowbase+i)*INNERD + kb + k4*4];
            Ast[(k4*4+0)*64 + i] = g.x;  Ast[(k4*4+1)*64 + i] = g.y;
            Ast[(k4*4+2)*64 + i] = g.z;  Ast[(k4*4+3)*64 + i] = g.w;
        }
        #pragma unroll
        for (int l = 0; l < 4; l++) {
            int e = l*256 + t, kk = e >> 5, c4 = e & 31;
            *(float4*)&Bs[kk*128 + c4*4] =
                *(const float4*)&wp[(kb+kk)*128 + c4*4];
        }
        __syncthreads();
        #pragma unroll
        for (int kk = 0; kk < 32; kk++) {
            float4 a  = *(float4*)&Ast[kk*64 + ty*4];
            float4 b0 = *(float4*)&Bs [kk*128 + tx*8];
            float4 b1 = *(float4*)&Bs [kk*128 + tx*8 + 4];
            float av[4] = {a.x, a.y, a.z, a.w};
            float bv[8] = {b0.x, b0.y, b0.z, b0.w, b1.x, b1.y, b1.z, b1.w};
            #pragma unroll
            for (int i = 0; i < 4; i++)
                #pragma unroll
                for (int c = 0; c < 8; c++) acc[i][c] += av[i] * bv[c];
        }
    }

    float4 bb0 = *(const float4*)&bias[tx*8];
    float4 bb1 = *(const float4*)&bias[tx*8 + 4];
    float bv[8] = {bb0.x, bb0.y, bb0.z, bb0.w, bb1.x, bb1.y, bb1.z, bb1.w};
    #pragma unroll
    for (int i = 0; i < 4; i++) {
        int row = rowbase + ty*4 + i;
        float4 o0 = make_float4(acc[i][0]+bv[0], acc[i][1]+bv[1], acc[i][2]+bv[2], acc[i][3]+bv[3]);
        float4 o1 = make_float4(acc[i][4]+bv[4], acc[i][5]+bv[5], acc[i][6]+bv[6], acc[i][7]+bv[7]);
        *(float4*)&out[row*128 + tx*8]     = o0;
        *(float4*)&out[row*128 + tx*8 + 4] = o1;
    }
}

// =============================== launch ===============================
extern "C" void kernel_launch(void* const* d_in, const int* in_sizes, int n_in,
                              void* d_out, int out_size) {
    const float* x      = (const float*)d_in[0];
    const float* ln_w   = (const float*)d_in[1];
    const float* ln_b   = (const float*)d_in[2];
    const float* w_qkv  = (const float*)d_in[3];
    const float* scale  = (const float*)d_in[4];
    const float* w_proj = (const float*)d_in[5];
    const float* b_proj = (const float*)d_in[6];
    float* out = (float*)d_out;

    // Idempotent attribute sets (non-stream API; safe under capture).
    cudaFuncSetAttribute(qkv_kernel,  cudaFuncAttributeMaxDynamicSharedMemorySize, 65536);
    cudaFuncSetAttribute(attn_kernel, cudaFuncAttributeMaxDynamicSharedMemorySize, 114944);

    ln_kernel  <<<ROWS_TOT, EMB>>>(x, ln_w, ln_b);
    qkv_kernel <<<dim3(48, 256), 256, 65536>>>(w_qkv);
    attn_kernel<<<dim3(16, 128), 256, 114944>>>(scale);
    proj_kernel<<<256, 256>>>(w_proj, b_proj, out);
}

// round 6
// speedup vs baseline: 1.0614x; 1.0614x over previous
#include <cuda_runtime.h>

#define BATCH  16
#define NPAT   1024
#define EMB    128
#define HEADS  8
#define ROWS_TOT (BATCH*NPAT)      /* 16384 */
#define INNERD   (EMB*HEADS)       /* 1024  */

// ---------------- scratch (static device allocations; allowed) ----------------
__device__ float g_xn[ROWS_TOT*EMB];                 //  8 MB  layernormed x
__device__ float g_q [BATCH*HEADS*NPAT*EMB];         // 64 MB  [bh][n][d]
__device__ float g_k [BATCH*HEADS*NPAT*EMB];         // 64 MB
__device__ float g_v [BATCH*HEADS*NPAT*EMB];         // 64 MB
__device__ float g_ao[ROWS_TOT*INNERD];              // 64 MB  [b*n][h*128+d]

// =============================== LayerNorm ===============================
__global__ void ln_kernel(const float* __restrict__ x,
                          const float* __restrict__ w,
                          const float* __restrict__ b) {
    int row = blockIdx.x, t = threadIdx.x;
    float v = x[row*EMB + t];
    float s = v;
    #pragma unroll
    for (int o = 16; o; o >>= 1) s += __shfl_xor_sync(0xffffffffu, s, o);
    __shared__ float r1[4], r2[4];
    if ((t & 31) == 0) r1[t >> 5] = s;
    __syncthreads();
    float mean = (r1[0] + r1[1] + r1[2] + r1[3]) * (1.0f/EMB);
    float d = v - mean;
    float q = d * d;
    #pragma unroll
    for (int o = 16; o; o >>= 1) q += __shfl_xor_sync(0xffffffffu, q, o);
    if ((t & 31) == 0) r2[t >> 5] = q;
    __syncthreads();
    float var = (r2[0] + r2[1] + r2[2] + r2[3]) * (1.0f/EMB);
    g_xn[row*EMB + t] = d * rsqrtf(var + 1e-5f) * w[t] + b[t];
}

// =============================== QKV GEMM ===============================
// C[16384,3072] = xn[16384,128] @ wqkv[128,3072], scattered into q/k/v head layout.
// 64x64 tile, 256 threads, 4x4 microtile, full K=128 in smem (k-major).
__global__ void __launch_bounds__(256) qkv_kernel(const float* __restrict__ wqkv) {
    extern __shared__ float sm[];
    float* Ast = sm;           // [128][64]  (xn transposed)
    float* Bs  = sm + 8192;    // [128][64]  (wqkv slice, already k-major)
    int t = threadIdx.x;
    int rowbase = blockIdx.y * 64;
    int colbase = blockIdx.x * 64;

    #pragma unroll
    for (int l = 0; l < 8; l++) {                 // transpose-load A
        int e = l*256 + t, i = e & 63, k4 = e >> 6;
        float4 g = *(const float4*)&g_xn[(rowbase+i)*EMB + k4*4];
        Ast[(k4*4+0)*64 + i] = g.x;  Ast[(k4*4+1)*64 + i] = g.y;
        Ast[(k4*4+2)*64 + i] = g.z;  Ast[(k4*4+3)*64 + i] = g.w;
    }
    #pragma unroll
    for (int l = 0; l < 8; l++) {                 // direct-load B
        int e = l*256 + t, k = e >> 4, j4 = e & 15;
        *(float4*)&Bs[k*64 + j4*4] =
            *(const float4*)&wqkv[k*3072 + colbase + j4*4];
    }
    __syncthreads();

    int ty = t >> 4, tx = t & 15;
    float acc[4][4] = {};
    #pragma unroll 8
    for (int k = 0; k < 128; k++) {
        float4 a = *(float4*)&Ast[k*64 + ty*4];
        float4 bb = *(float4*)&Bs [k*64 + tx*4];
        float av[4] = {a.x, a.y, a.z, a.w};
        float bv[4] = {bb.x, bb.y, bb.z, bb.w};
        #pragma unroll
        for (int i = 0; i < 4; i++)
            #pragma unroll
            for (int jj = 0; jj < 4; jj++) acc[i][jj] += av[i] * bv[jj];
    }

    int section = colbase >> 10;          // 0:q 1:k 2:v (64-col tile never straddles)
    int h     = (colbase & 1023) >> 7;
    int dbase = colbase & 127;
    float* dst = (section == 0) ? g_q : ((section == 1) ? g_k : g_v);
    #pragma unroll
    for (int i = 0; i < 4; i++) {
        int row = rowbase + ty*4 + i;
        int bb = row >> 10, n = row & 1023;
        float4 o = make_float4(acc[i][0], acc[i][1], acc[i][2], acc[i][3]);
        *(float4*)&dst[((bb*HEADS + h)*NPAT + n)*EMB + dbase + tx*4] = o;
    }
}

// ====================== Flash attention (per 64-query tile) ======================
// grid (16 qtiles, 128 bh), 256 threads. Online softmax, diag masked to -FLT_MAX.
__global__ void __launch_bounds__(256) attn_kernel(const float* __restrict__ scale) {
    extern __shared__ float sm[];
    float* Qst = sm;            // [128][64]  Q^T * scale
    float* Kst = sm + 8192;     // [128][64]  K^T
    float* Vs  = sm + 16384;    // [64][128]  V
    float* Pst = sm + 24576;    // [64][65]   P^T (padded stride 65)
    int t = threadIdx.x;
    int bh = blockIdx.y;
    int qbase = blockIdx.x * 64;
    const float* Qg  = g_q + (bh*NPAT + qbase)*EMB;
    const float* Kg0 = g_k + bh*NPAT*EMB;
    const float* Vg0 = g_v + bh*NPAT*EMB;
    float sc = scale[bh & (HEADS-1)];

    #pragma unroll
    for (int l = 0; l < 8; l++) {                 // Q transpose + scale fold
        int e = l*256 + t, i = e & 63, k4 = e >> 6;
        float4 g = *(const float4*)&Qg[i*EMB + k4*4];
        Qst[(k4*4+0)*64 + i] = g.x*sc;  Qst[(k4*4+1)*64 + i] = g.y*sc;
        Qst[(k4*4+2)*64 + i] = g.z*sc;  Qst[(k4*4+3)*64 + i] = g.w*sc;
    }

    int ty = t >> 4, tx = t & 15;
    float m[4], lsum[4], acc[4][8];
    #pragma unroll
    for (int i = 0; i < 4; i++) {
        m[i] = -3.402823466e38f; lsum[i] = 0.f;
        #pragma unroll
        for (int c = 0; c < 8; c++) acc[i][c] = 0.f;
    }

    for (int j = 0; j < 16; j++) {
        __syncthreads();                          // prev iter smem reads done
        const float* Kg = Kg0 + j*64*EMB;
        const float* Vg = Vg0 + j*64*EMB;
        #pragma unroll
        for (int l = 0; l < 8; l++) {             // K transpose (conflict-free STS)
            int e = l*256 + t, i = e & 63, k4 = e >> 6;
            float4 g = *(const float4*)&Kg[i*EMB + k4*4];
            Kst[(k4*4+0)*64 + i] = g.x;  Kst[(k4*4+1)*64 + i] = g.y;
            Kst[(k4*4+2)*64 + i] = g.z;  Kst[(k4*4+3)*64 + i] = g.w;
        }
        #pragma unroll
        for (int l = 0; l < 8; l++) {             // V direct copy
            int e = l*256 + t, r = e >> 5, c4 = e & 31;
            *(float4*)&Vs[r*EMB + c4*4] = *(const float4*)&Vg[r*EMB + c4*4];
        }
        __syncthreads();

        // ---- S = (Q*sc) K^T  (64x64, 4x4 per thread) ----
        float s[4][4] = {};
        #pragma unroll 8
        for (int k = 0; k < 128; k++) {
            float4 a = *(float4*)&Qst[k*64 + ty*4];
            float4 b = *(float4*)&Kst[k*64 + tx*4];
            float av[4] = {a.x, a.y, a.z, a.w};
            float bv[4] = {b.x, b.y, b.z, b.w};
            #pragma unroll
            for (int i = 0; i < 4; i++)
                #pragma unroll
                for (int jj = 0; jj < 4; jj++) s[i][jj] += av[i] * bv[jj];
        }

        // ---- diagonal mask (only the matching tile can contain it) ----
        if (j == (int)blockIdx.x) {
            int row0 = qbase + ty*4, col0 = j*64 + tx*4;
            #pragma unroll
            for (int i = 0; i < 4; i++)
                #pragma unroll
                for (int jj = 0; jj < 4; jj++)
                    if (row0 + i == col0 + jj) s[i][jj] = -3.402823466e38f;
        }

        // ---- online softmax (row reductions via 16-lane shfl groups) ----
        #pragma unroll
        for (int i = 0; i < 4; i++) {
            float rm = fmaxf(fmaxf(s[i][0], s[i][1]), fmaxf(s[i][2], s[i][3]));
            #pragma unroll
            for (int o = 1; o < 16; o <<= 1)
                rm = fmaxf(rm, __shfl_xor_sync(0xffffffffu, rm, o));
            float mn   = fmaxf(m[i], rm);
            float corr = __expf(m[i] - mn);
            m[i] = mn;
            float rs = 0.f;
            #pragma unroll
            for (int jj = 0; jj < 4; jj++) { s[i][jj] = __expf(s[i][jj] - mn); rs += s[i][jj]; }
            #pragma unroll
            for (int o = 1; o < 16; o <<= 1)
                rs += __shfl_xor_sync(0xffffffffu, rs, o);
            lsum[i] = lsum[i]*corr + rs;
            #pragma unroll
            for (int c = 0; c < 8; c++) acc[i][c] *= corr;
        }

        // ---- stash P^T to smem (stride 65 -> at most 2-way conflicts) ----
        #pragma unroll
        for (int i = 0; i < 4; i++)
            #pragma unroll
            for (int jj = 0; jj < 4; jj++)
                Pst[(tx*4 + jj)*65 + ty*4 + i] = s[i][jj];
        __syncthreads();

        // ---- O += P V  (64x128, 4x8 per thread) ----
        #pragma unroll 8
        for (int k = 0; k < 64; k++) {
            float p[4];
            #pragma unroll
            for (int i = 0; i < 4; i++) p[i] = Pst[k*65 + ty*4 + i];
            float4 v0 = *(float4*)&Vs[k*EMB + tx*8];
            float4 v1 = *(float4*)&Vs[k*EMB + tx*8 + 4];
            float vv[8] = {v0.x, v0.y, v0.z, v0.w, v1.x, v1.y, v1.z, v1.w};
            #pragma unroll
            for (int i = 0; i < 4; i++)
                #pragma unroll
                for (int c = 0; c < 8; c++) acc[i][c] += p[i] * vv[c];
        }
    }

    // ---- epilogue: normalize and write [b][n][h*128+d] ----
    int bb = bh >> 3, h = bh & 7;
    #pragma unroll
    for (int i = 0; i < 4; i++) {
        float inv = 1.0f / lsum[i];
        int n = qbase + ty*4 + i;
        float* op = g_ao + (bb*NPAT + n)*INNERD + h*EMB + tx*8;
        float4 o0 = make_float4(acc[i][0]*inv, acc[i][1]*inv, acc[i][2]*inv, acc[i][3]*inv);
        float4 o1 = make_float4(acc[i][4]*inv, acc[i][5]*inv, acc[i][6]*inv, acc[i][7]*inv);
        *(float4*)&op[0] = o0;
        *(float4*)&op[4] = o1;
    }
}

// =============================== Output projection ===============================
// out[16384,128] = g_ao[16384,1024] @ wp[1024,128] + bias. 64x128 tile, BK=32.
__global__ void __launch_bounds__(256) proj_kernel(const float* __restrict__ wp,
                                                   const float* __restrict__ bias,
                                                   float* __restrict__ out) {
    __shared__ float Ast[32*64];    // A^T chunk
    __shared__ float Bs [32*128];   // W chunk (k-major already)
    int t = threadIdx.x;
    int rowbase = blockIdx.x * 64;
    int ty = t >> 4, tx = t & 15;
    float acc[4][8] = {};

    for (int kb = 0; kb < 1024; kb += 32) {
        __syncthreads();
        #pragma unroll
        for (int l = 0; l < 2; l++) {
            int e = l*256 + t, i = e & 63, k4 = e >> 6;   // k4 in 0..7
            float4 g = *(const float4*)&g_ao[(rowbase+i)*INNERD + kb + k4*4];
            Ast[(k4*4+0)*64 + i] = g.x;  Ast[(k4*4+1)*64 + i] = g.y;
            Ast[(k4*4+2)*64 + i] = g.z;  Ast[(k4*4+3)*64 + i] = g.w;
        }
        #pragma unroll
        for (int l = 0; l < 4; l++) {
            int e = l*256 + t, kk = e >> 5, c4 = e & 31;
            *(float4*)&Bs[kk*128 + c4*4] =
                *(const float4*)&wp[(kb+kk)*128 + c4*4];
        }
        __syncthreads();
        #pragma unroll
        for (int kk = 0; kk < 32; kk++) {
            float4 a  = *(float4*)&Ast[kk*64 + ty*4];
            float4 b0 = *(float4*)&Bs [kk*128 + tx*8];
            float4 b1 = *(float4*)&Bs [kk*128 + tx*8 + 4];
            float av[4] = {a.x, a.y, a.z, a.w};
            float bv[8] = {b0.x, b0.y, b0.z, b0.w, b1.x, b1.y, b1.z, b1.w};
            #pragma unroll
            for (int i = 0; i < 4; i++)
                #pragma unroll
                for (int c = 0; c < 8; c++) acc[i][c] += av[i] * bv[c];
        }
    }

    float4 bb0 = *(const float4*)&bias[tx*8];
    float4 bb1 = *(const float4*)&bias[tx*8 + 4];
    float bv[8] = {bb0.x, bb0.y, bb0.z, bb0.w, bb1.x, bb1.y, bb1.z, bb1.w};
    #pragma unroll
    for (int i = 0; i < 4; i++) {
        int row = rowbase + ty*4 + i;
        float4 o0 = make_float4(acc[i][0]+bv[0], acc[i][1]+bv[1], acc[i][2]+bv[2], acc[i][3]+bv[3]);
        float4 o1 = make_float4(acc[i][4]+bv[4], acc[i][5]+bv[5], acc[i][6]+bv[6], acc[i][7]+bv[7]);
        *(float4*)&out[row*128 + tx*8]     = o0;
        *(float4*)&out[row*128 + tx*8 + 4] = o1;
    }
}

// =============================== launch ===============================
extern "C" void kernel_launch(void* const* d_in, const int* in_sizes, int n_in,
                              void* d_out, int out_size) {
    const float* x      = (const float*)d_in[0];
    const float* ln_w   = (const float*)d_in[1];
    const float* ln_b   = (const float*)d_in[2];
    const float* w_qkv  = (const float*)d_in[3];
    const float* scale  = (const float*)d_in[4];
    const float* w_proj = (const float*)d_in[5];
    const float* b_proj = (const float*)d_in[6];
    float* out = (float*)d_out;

    // Idempotent attribute sets (non-stream API; safe under capture).
    cudaFuncSetAttribute(qkv_kernel,  cudaFuncAttributeMaxDynamicSharedMemorySize, 65536);
    cudaFuncSetAttribute(attn_kernel, cudaFuncAttributeMaxDynamicSharedMemorySize, 114944);

    ln_kernel  <<<ROWS_TOT, EMB>>>(x, ln_w, ln_b);
    qkv_kernel <<<dim3(48, 256), 256, 65536>>>(w_qkv);
    attn_kernel<<<dim3(16, 128), 256, 114944>>>(scale);
    proj_kernel<<<256, 256>>>(w_proj, b_proj, out);
}

// round 10
// speedup vs baseline: 2.4169x; 2.2770x over previous
#include <cuda_runtime.h>
#include <cuda_bf16.h>
#include <cstdint>

#define BATCH  16
#define NPAT   1024
#define EMB    128
#define HEADS  8
#define ROWS_TOT (BATCH*NPAT)      /* 16384 */
#define INNERD   (EMB*HEADS)       /* 1024  */
#define FLTMAX 3.402823466e38f

// ---------------- scratch (static device allocations; allowed) ----------------
__device__ float g_xn[ROWS_TOT*EMB];
__device__ float g_q [BATCH*HEADS*NPAT*EMB];
__device__ float g_k [BATCH*HEADS*NPAT*EMB];
__device__ float g_v [BATCH*HEADS*NPAT*EMB];
__device__ float g_ao[ROWS_TOT*INNERD];

// ====================== warp-MMA helpers (base sm_103-safe) ======================
__device__ __forceinline__ uint32_t smem_u32(const void* p) {
    uint32_t a;
    asm("{ .reg .u64 t; cvta.to.shared.u64 t, %1; cvt.u32.u64 %0, t; }" : "=r"(a) : "l"(p));
    return a;
}
__device__ __forceinline__ void ldsm4(uint32_t* r, uint32_t a) {
    asm volatile("ldmatrix.sync.aligned.m8n8.x4.shared.b16 {%0,%1,%2,%3}, [%4];"
        : "=r"(r[0]), "=r"(r[1]), "=r"(r[2]), "=r"(r[3]) : "r"(a));
}
__device__ __forceinline__ void ldsm2(uint32_t* r, uint32_t a) {
    asm volatile("ldmatrix.sync.aligned.m8n8.x2.shared.b16 {%0,%1}, [%2];"
        : "=r"(r[0]), "=r"(r[1]) : "r"(a));
}
// D(m16n8,f32) += A(m16k16,row,bf16) * B(k16n8,col,bf16)
__device__ __forceinline__ void mma16816(float* d, const uint32_t* a, const uint32_t* b) {
    asm volatile("mma.sync.aligned.m16n8k16.row.col.f32.bf16.bf16.f32 "
        "{%0,%1,%2,%3}, {%4,%5,%6,%7}, {%8,%9}, {%0,%1,%2,%3};"
        : "+f"(d[0]), "+f"(d[1]), "+f"(d[2]), "+f"(d[3])
        : "r"(a[0]), "r"(a[1]), "r"(a[2]), "r"(a[3]), "r"(b[0]), "r"(b[1]));
}
__device__ __forceinline__ uint32_t bfpack(__nv_bfloat16 a, __nv_bfloat16 b) {
    __nv_bfloat162 t = __halves2bfloat162(a, b);   // low half = a
    return *reinterpret_cast<uint32_t*>(&t);
}
__device__ __forceinline__ void bsplit(float x, __nv_bfloat16& h, __nv_bfloat16& l) {
    h = __float2bfloat16(x);
    l = __float2bfloat16(x - __bfloat162float(h));
}

// ---------------- attention SMEM map (bytes) ----------------
// Q: [128][128]bf16 swizzled (32KB each hi/lo). K: [64][128] (16KB each).
// Vt: [128 d][64 s] (16KB each). stage: fp32 [64][132] (33792B).
#define AT_QH 0
#define AT_QL 32768
#define AT_KH 65536
#define AT_KL 81920
#define AT_VH 98304
#define AT_VL 114688
#define AT_ST 131072
#define SMEM_ATTN (131072 + 33792)

// =============================== LayerNorm ===============================
__global__ void ln_kernel(const float* __restrict__ x,
                          const float* __restrict__ w,
                          const float* __restrict__ b) {
    int row = blockIdx.x, t = threadIdx.x;
    float v = x[row*EMB + t];
    float s = v;
    #pragma unroll
    for (int o = 16; o; o >>= 1) s += __shfl_xor_sync(0xffffffffu, s, o);
    __shared__ float r1[4], r2[4];
    if ((t & 31) == 0) r1[t >> 5] = s;
    __syncthreads();
    float mean = (r1[0] + r1[1] + r1[2] + r1[3]) * (1.0f/EMB);
    float d = v - mean;
    float q = d * d;
    #pragma unroll
    for (int o = 16; o; o >>= 1) q += __shfl_xor_sync(0xffffffffu, q, o);
    if ((t & 31) == 0) r2[t >> 5] = q;
    __syncthreads();
    float var = (r2[0] + r2[1] + r2[2] + r2[3]) * (1.0f/EMB);
    g_xn[row*EMB + t] = d * rsqrtf(var + 1e-5f) * w[t] + b[t];
}

// =============================== QKV GEMM (fp32) ===============================
__global__ void __launch_bounds__(256) qkv_kernel(const float* __restrict__ wqkv) {
    extern __shared__ float sm[];
    float* Ast = sm;
    float* Bs  = sm + 8192;
    int t = threadIdx.x;
    int rowbase = blockIdx.y * 64;
    int colbase = blockIdx.x * 64;

    #pragma unroll
    for (int l = 0; l < 8; l++) {
        int e = l*256 + t, i = e & 63, k4 = e >> 6;
        float4 g = *(const float4*)&g_xn[(rowbase+i)*EMB + k4*4];
        Ast[(k4*4+0)*64 + i] = g.x;  Ast[(k4*4+1)*64 + i] = g.y;
        Ast[(k4*4+2)*64 + i] = g.z;  Ast[(k4*4+3)*64 + i] = g.w;
    }
    #pragma unroll
    for (int l = 0; l < 8; l++) {
        int e = l*256 + t, k = e >> 4, j4 = e & 15;
        *(float4*)&Bs[k*64 + j4*4] = *(const float4*)&wqkv[k*3072 + colbase + j4*4];
    }
    __syncthreads();

    int ty = t >> 4, tx = t & 15;
    float acc[4][4] = {};
    #pragma unroll 8
    for (int k = 0; k < 128; k++) {
        float4 a = *(float4*)&Ast[k*64 + ty*4];
        float4 bb = *(float4*)&Bs [k*64 + tx*4];
        float av[4] = {a.x, a.y, a.z, a.w};
        float bv[4] = {bb.x, bb.y, bb.z, bb.w};
        #pragma unroll
        for (int i = 0; i < 4; i++)
            #pragma unroll
            for (int jj = 0; jj < 4; jj++) acc[i][jj] += av[i] * bv[jj];
    }

    int section = colbase >> 10;
    int h     = (colbase & 1023) >> 7;
    int dbase = colbase & 127;
    float* dst = (section == 0) ? g_q : ((section == 1) ? g_k : g_v);
    #pragma unroll
    for (int i = 0; i < 4; i++) {
        int row = rowbase + ty*4 + i;
        int bb = row >> 10, n = row & 1023;
        *(float4*)&dst[((bb*HEADS + h)*NPAT + n)*EMB + dbase + tx*4] =
            make_float4(acc[i][0], acc[i][1], acc[i][2], acc[i][3]);
    }
}

// ====================== mma.sync flash attention ======================
// grid (8 q-tiles, 128 bh), 256 threads (8 warps x 16 q-rows), 1 CTA/SM.
// bf16 hi/lo split (3 mma per product) -> err ~1e-5. P stays in registers.
__global__ void __launch_bounds__(256, 1) attn_mma(const float* __restrict__ scale) {
    extern __shared__ char smc[];
    uint32_t sb = smem_u32(smc);
    float* stage = (float*)(smc + AT_ST);
    int tid = threadIdx.x, w = tid >> 5, L = tid & 31;
    int qt = blockIdx.x, bh = blockIdx.y;
    int qbase = qt * 128;
    const float* Qg  = g_q + (size_t)(bh*NPAT + qbase)*EMB;
    const float* Kg0 = g_k + (size_t)bh*NPAT*EMB;
    const float* Vg0 = g_v + (size_t)bh*NPAT*EMB;
    float sc = scale[bh & (HEADS-1)];

    // ---- Q -> Qhi/Qlo, swizzled k-major [row][128], scale folded ----
    #pragma unroll
    for (int it = 0; it < 8; it++) {
        int e = it*256 + tid, row = e >> 4, c16 = e & 15;
        const float* src = Qg + row*EMB + c16*8;
        float4 f0 = *(const float4*)src, f1 = *(const float4*)(src + 4);
        float f[8] = {f0.x, f0.y, f0.z, f0.w, f1.x, f1.y, f1.z, f1.w};
        uint32_t hi[4], lo[4];
        #pragma unroll
        for (int p = 0; p < 4; p++) {
            __nv_bfloat16 ha, la, hb, lb;
            bsplit(f[2*p]*sc, ha, la); bsplit(f[2*p+1]*sc, hb, lb);
            hi[p] = bfpack(ha, hb);  lo[p] = bfpack(la, lb);
        }
        uint32_t off = (uint32_t)(row*256 + ((c16 ^ (row & 7)) << 4));
        *(uint4*)(smc + AT_QH + off) = make_uint4(hi[0], hi[1], hi[2], hi[3]);
        *(uint4*)(smc + AT_QL + off) = make_uint4(lo[0], lo[1], lo[2], lo[3]);
    }

    // per-lane fragment address invariants
    int l7  = L & 7;
    int rowA = (w << 4) + ((L >> 3) & 1)*8 + l7;   // A-frag row (rowA&7 == l7)
    int cA  = L >> 4;                               // A chunk offset (0/1)
    uint32_t aBaseH = sb + AT_QH + rowA*256;
    uint32_t aBaseL = sb + AT_QL + rowA*256;
    int Lb  = L & 15;                               // ldmatrix.x2 uses lanes 0-15
    int bl7 = Lb & 7;
    int cB  = Lb >> 3;                              // B chunk offset (0/1)

    int g  = L >> 2;                                // C-frag row group
    int t2 = (L & 3)*2;                             // C-frag col pair
    int rg0 = qbase + (w << 4) + g;                 // global q rows this lane owns
    int rg1 = rg0 + 8;

    float m0 = -FLTMAX, m1 = -FLTMAX, ls0 = 0.f, ls1 = 0.f;
    float O[16][4];
    #pragma unroll
    for (int nb = 0; nb < 16; nb++)
        #pragma unroll
        for (int e = 0; e < 4; e++) O[nb][e] = 0.f;

    #pragma unroll 1
    for (int j = 0; j < 16; j++) {
        __syncthreads();   // prev-iter Vt/K fragment loads complete
        const float* Kg = Kg0 + (size_t)j*64*EMB;
        const float* Vg = Vg0 + (size_t)j*64*EMB;

        // ---- K -> Khi/Klo swizzled ----
        #pragma unroll
        for (int it = 0; it < 4; it++) {
            int e = it*256 + tid, row = e >> 4, c16 = e & 15;
            const float* src = Kg + row*EMB + c16*8;
            float4 f0 = *(const float4*)src, f1 = *(const float4*)(src + 4);
            float f[8] = {f0.x, f0.y, f0.z, f0.w, f1.x, f1.y, f1.z, f1.w};
            uint32_t hi[4], lo[4];
            #pragma unroll
            for (int p = 0; p < 4; p++) {
                __nv_bfloat16 ha, la, hb, lb;
                bsplit(f[2*p], ha, la); bsplit(f[2*p+1], hb, lb);
                hi[p] = bfpack(ha, hb);  lo[p] = bfpack(la, lb);
            }
            uint32_t off = (uint32_t)(row*256 + ((c16 ^ (row & 7)) << 4));
            *(uint4*)(smc + AT_KH + off) = make_uint4(hi[0], hi[1], hi[2], hi[3]);
            *(uint4*)(smc + AT_KL + off) = make_uint4(lo[0], lo[1], lo[2], lo[3]);
        }
        // ---- V -> fp32 stage (coalesced) ----
        #pragma unroll
        for (int it = 0; it < 8; it++) {
            int e = it*256 + tid, row = e >> 5, c4 = e & 31;
            *(float4*)&stage[row*132 + c4*4] = *(const float4*)&Vg[row*EMB + c4*4];
        }
        __syncthreads();

        // ---- transpose V: stage[s][d] -> Vt[d][s] hi/lo swizzled ----
        #pragma unroll
        for (int it = 0; it < 4; it++) {
            int e = it*256 + tid, d = e & 127, c8 = e >> 7;
            uint32_t hi[4], lo[4];
            #pragma unroll
            for (int p = 0; p < 4; p++) {
                float fa = stage[(c8*8 + 2*p    )*132 + d];
                float fb = stage[(c8*8 + 2*p + 1)*132 + d];
                __nv_bfloat16 ha, la, hb, lb;
                bsplit(fa, ha, la); bsplit(fb, hb, lb);
                hi[p] = bfpack(ha, hb);  lo[p] = bfpack(la, lb);
            }
            uint32_t off = (uint32_t)(d*128 + ((c8 ^ (d & 7)) << 4));
            *(uint4*)(smc + AT_VH + off) = make_uint4(hi[0], hi[1], hi[2], hi[3]);
            *(uint4*)(smc + AT_VL + off) = make_uint4(lo[0], lo[1], lo[2], lo[3]);
        }

        // ---- S = (Q*sc) K^T : m16 x n64 per warp, k=128 ----
        float S[8][4];
        #pragma unroll
        for (int nb = 0; nb < 8; nb++)
            #pragma unroll
            for (int e = 0; e < 4; e++) S[nb][e] = 0.f;

        #pragma unroll
        for (int kc = 0; kc < 8; kc++) {
            uint32_t aqh[4], aql[4];
            uint32_t aphys = (uint32_t)(((kc*2 + cA) ^ l7) << 4);
            ldsm4(aqh, aBaseH + aphys);
            ldsm4(aql, aBaseL + aphys);
            #pragma unroll
            for (int nb = 0; nb < 8; nb++) {
                uint32_t bhf[2], blf[2];
                uint32_t boff = (uint32_t)((nb*8 + bl7)*256 + (((kc*2 + cB) ^ bl7) << 4));
                ldsm2(bhf, sb + AT_KH + boff);
                ldsm2(blf, sb + AT_KL + boff);
                mma16816(S[nb], aqh, bhf);
                mma16816(S[nb], aqh, blf);
                mma16816(S[nb], aql, bhf);
            }
        }

        // ---- diagonal mask (fully unrolled; no dynamic reg indexing) ----
        if ((j >> 1) == qt) {
            int colbase = j*64;
            #pragma unroll
            for (int nb = 0; nb < 8; nb++) {
                int c0 = colbase + nb*8 + t2;
                if (c0     == rg0) S[nb][0] = -FLTMAX;
                if (c0 + 1 == rg0) S[nb][1] = -FLTMAX;
                if (c0     == rg1) S[nb][2] = -FLTMAX;
                if (c0 + 1 == rg1) S[nb][3] = -FLTMAX;
            }
        }

        // ---- online softmax (quad-lane row reductions) ----
        float rmax0 = -FLTMAX, rmax1 = -FLTMAX;
        #pragma unroll
        for (int nb = 0; nb < 8; nb++) {
            rmax0 = fmaxf(rmax0, fmaxf(S[nb][0], S[nb][1]));
            rmax1 = fmaxf(rmax1, fmaxf(S[nb][2], S[nb][3]));
        }
        rmax0 = fmaxf(rmax0, __shfl_xor_sync(0xffffffffu, rmax0, 1));
        rmax0 = fmaxf(rmax0, __shfl_xor_sync(0xffffffffu, rmax0, 2));
        rmax1 = fmaxf(rmax1, __shfl_xor_sync(0xffffffffu, rmax1, 1));
        rmax1 = fmaxf(rmax1, __shfl_xor_sync(0xffffffffu, rmax1, 2));
        float mn0 = fmaxf(m0, rmax0), mn1 = fmaxf(m1, rmax1);
        float cr0 = __expf(m0 - mn0), cr1 = __expf(m1 - mn1);
        m0 = mn0; m1 = mn1;
        float rs0 = 0.f, rs1 = 0.f;
        #pragma unroll
        for (int nb = 0; nb < 8; nb++) {
            S[nb][0] = __expf(S[nb][0] - mn0); rs0 += S[nb][0];
            S[nb][1] = __expf(S[nb][1] - mn0); rs0 += S[nb][1];
            S[nb][2] = __expf(S[nb][2] - mn1); rs1 += S[nb][2];
            S[nb][3] = __expf(S[nb][3] - mn1); rs1 += S[nb][3];
        }
        rs0 += __shfl_xor_sync(0xffffffffu, rs0, 1);
        rs0 += __shfl_xor_sync(0xffffffffu, rs0, 2);
        rs1 += __shfl_xor_sync(0xffffffffu, rs1, 1);
        rs1 += __shfl_xor_sync(0xffffffffu, rs1, 2);
        ls0 = ls0*cr0 + rs0;
        ls1 = ls1*cr1 + rs1;
        #pragma unroll
        for (int nb = 0; nb < 16; nb++) {
            O[nb][0] *= cr0;  O[nb][1] *= cr0;
            O[nb][2] *= cr1;  O[nb][3] *= cr1;
        }

        __syncthreads();   // Vt ready

        // ---- O += P V : P (regs) hi/lo -> A-frags; B from Vt ----
        #pragma unroll
        for (int kc = 0; kc < 4; kc++) {
            uint32_t ah[4], al[4];
            {
                __nv_bfloat16 hx, lx, hy, ly;
                bsplit(S[2*kc][0], hx, lx);   bsplit(S[2*kc][1], hy, ly);
                ah[0] = bfpack(hx, hy);  al[0] = bfpack(lx, ly);
                bsplit(S[2*kc][2], hx, lx);   bsplit(S[2*kc][3], hy, ly);
                ah[1] = bfpack(hx, hy);  al[1] = bfpack(lx, ly);
                bsplit(S[2*kc+1][0], hx, lx); bsplit(S[2*kc+1][1], hy, ly);
                ah[2] = bfpack(hx, hy);  al[2] = bfpack(lx, ly);
                bsplit(S[2*kc+1][2], hx, lx); bsplit(S[2*kc+1][3], hy, ly);
                ah[3] = bfpack(hx, hy);  al[3] = bfpack(lx, ly);
            }
            #pragma unroll
            for (int nb = 0; nb < 16; nb++) {
                uint32_t bhf[2], blf[2];
                uint32_t off = (uint32_t)((nb*8 + bl7)*128 + (((kc*2 + cB) ^ bl7) << 4));
                ldsm2(bhf, sb + AT_VH + off);
                ldsm2(blf, sb + AT_VL + off);
                mma16816(O[nb], ah, bhf);
                mma16816(O[nb], ah, blf);
                mma16816(O[nb], al, bhf);
            }
        }
    }

    // ---- epilogue: normalize, write g_ao[b][n][h*128 + col] ----
    float inv0 = 1.0f / ls0, inv1 = 1.0f / ls1;
    int bb = bh >> 3, h = bh & 7;
    float* o0 = g_ao + (size_t)(bb*NPAT + rg0)*INNERD + h*EMB;
    float* o1 = g_ao + (size_t)(bb*NPAT + rg1)*INNERD + h*EMB;
    #pragma unroll
    for (int nb = 0; nb < 16; nb++) {
        int col = nb*8 + t2;
        *(float2*)&o0[col] = make_float2(O[nb][0]*inv0, O[nb][1]*inv0);
        *(float2*)&o1[col] = make_float2(O[nb][2]*inv1, O[nb][3]*inv1);
    }
}

// =============================== Output projection (fp32) ===============================
__global__ void __launch_bounds__(256) proj_kernel(const float* __restrict__ wp,
                                                   const float* __restrict__ bias,
                                                   float* __restrict__ out) {
    __shared__ float Ast[32*64];
    __shared__ float Bs [32*128];
    int t = threadIdx.x;
    int rowbase = blockIdx.x * 64;
    int ty = t >> 4, tx = t & 15;
    float acc[4][8] = {};

    for (int kb = 0; kb < 1024; kb += 32) {
        __syncthreads();
        #pragma unroll
        for (int l = 0; l < 2; l++) {
            int e = l*256 + t, i = e & 63, k4 = e >> 6;
            float4 g = *(const float4*)&g_ao[(rowbase+i)*INNERD + kb + k4*4];
            Ast[(k4*4+0)*64 + i] = g.x;  Ast[(k4*4+1)*64 + i] = g.y;
            Ast[(k4*4+2)*64 + i] = g.z;  Ast[(k4*4+3)*64 + i] = g.w;
        }
        #pragma unroll
        for (int l = 0; l < 4; l++) {
            int e = l*256 + t, kk = e >> 5, c4 = e & 31;
            *(float4*)&Bs[kk*128 + c4*4] = *(const float4*)&wp[(kb+kk)*128 + c4*4];
        }
        __syncthreads();
        #pragma unroll
        for (int kk = 0; kk < 32; kk++) {
            float4 a  = *(float4*)&Ast[kk*64 + ty*4];
            float4 b0 = *(float4*)&Bs [kk*128 + tx*8];
            float4 b1 = *(float4*)&Bs [kk*128 + tx*8 + 4];
            float av[4] = {a.x, a.y, a.z, a.w};
            float bv[8] = {b0.x, b0.y, b0.z, b0.w, b1.x, b1.y, b1.z, b1.w};
            #pragma unroll
            for (int i = 0; i < 4; i++)
                #pragma unroll
                for (int c = 0; c < 8; c++) acc[i][c] += av[i] * bv[c];
        }
    }

    float4 bb0 = *(const float4*)&bias[tx*8];
    float4 bb1 = *(const float4*)&bias[tx*8 + 4];
    float bv[8] = {bb0.x, bb0.y, bb0.z, bb0.w, bb1.x, bb1.y, bb1.z, bb1.w};
    #pragma unroll
    for (int i = 0; i < 4; i++) {
        int row = rowbase + ty*4 + i;
        *(float4*)&out[row*128 + tx*8] =
            make_float4(acc[i][0]+bv[0], acc[i][1]+bv[1], acc[i][2]+bv[2], acc[i][3]+bv[3]);
        *(float4*)&out[row*128 + tx*8 + 4] =
            make_float4(acc[i][4]+bv[4], acc[i][5]+bv[5], acc[i][6]+bv[6], acc[i][7]+bv[7]);
    }
}

// =============================== launch ===============================
extern "C" void kernel_launch(void* const* d_in, const int* in_sizes, int n_in,
                              void* d_out, int out_size) {
    const float* x      = (const float*)d_in[0];
    const float* ln_w   = (const float*)d_in[1];
    const float* ln_b   = (const float*)d_in[2];
    const float* w_qkv  = (const float*)d_in[3];
    const float* scale  = (const float*)d_in[4];
    const float* w_proj = (const float*)d_in[5];
    const float* b_proj = (const float*)d_in[6];
    float* out = (float*)d_out;

    cudaFuncSetAttribute(qkv_kernel, cudaFuncAttributeMaxDynamicSharedMemorySize, 65536);
    cudaFuncSetAttribute(attn_mma,   cudaFuncAttributeMaxDynamicSharedMemorySize, SMEM_ATTN);

    ln_kernel  <<<ROWS_TOT, EMB>>>(x, ln_w, ln_b);
    qkv_kernel <<<dim3(48, 256), 256, 65536>>>(w_qkv);
    attn_mma   <<<dim3(8, 128), 256, SMEM_ATTN>>>(scale);
    proj_kernel<<<256, 256>>>(w_proj, b_proj, out);
}

// round 11
// speedup vs baseline: 4.5350x; 1.8764x over previous
#include <cuda_runtime.h>
#include <cuda_bf16.h>
#include <cstdint>

#define BATCH  16
#define NPAT   1024
#define EMB    128
#define HEADS  8
#define ROWS_TOT (BATCH*NPAT)      /* 16384 */
#define INNERD   (EMB*HEADS)       /* 1024  */
#define FLTMAX 3.402823466e38f

// ---------------- scratch (static device allocations; allowed) ----------------
// All bf16 tile stores are PRE-SWIZZLED in the exact smem layout the consumers use,
// so every consumer copy is a linear 16B cp.async.
__device__ uint4 g_xnh[4194304/16],  g_xnl[4194304/16];    // xn  [128 rt][128r][128d]  4MB each
__device__ uint4 g_qh [33554432/16], g_ql [33554432/16];   // Q   [128 bh][8 qt][128][128d] 32MB
__device__ uint4 g_kh [33554432/16], g_kl [33554432/16];   // K   [128 bh][16 jt][64][128d]
__device__ uint4 g_vth[33554432/16], g_vtl[33554432/16];   // Vt  [128 bh][16 jt][128d][64s]
__device__ uint4 g_aoh[33554432/16], g_aol[33554432/16];   // O   [128 rt][128r][1024k]
__device__ uint4 g_wqh[786432/16],   g_wql[786432/16];     // wqkv^T [3072 n][128 k]
__device__ uint4 g_wph[262144/16],   g_wpl[262144/16];     // wproj^T [128 d][1024 k]

// ====================== PTX helpers ======================
__device__ __forceinline__ uint32_t smem_u32(const void* p) {
    uint32_t a;
    asm("{ .reg .u64 t; cvta.to.shared.u64 t, %1; cvt.u32.u64 %0, t; }" : "=r"(a) : "l"(p));
    return a;
}
__device__ __forceinline__ void ldsm4(uint32_t* r, uint32_t a) {
    asm volatile("ldmatrix.sync.aligned.m8n8.x4.shared.b16 {%0,%1,%2,%3}, [%4];"
        : "=r"(r[0]), "=r"(r[1]), "=r"(r[2]), "=r"(r[3]) : "r"(a));
}
__device__ __forceinline__ void mma16816(float* d, const uint32_t* a, const uint32_t* b) {
    asm volatile("mma.sync.aligned.m16n8k16.row.col.f32.bf16.bf16.f32 "
        "{%0,%1,%2,%3}, {%4,%5,%6,%7}, {%8,%9}, {%0,%1,%2,%3};"
        : "+f"(d[0]), "+f"(d[1]), "+f"(d[2]), "+f"(d[3])
        : "r"(a[0]), "r"(a[1]), "r"(a[2]), "r"(a[3]), "r"(b[0]), "r"(b[1]));
}
__device__ __forceinline__ void cpa16(uint32_t dst, const void* src) {
    asm volatile("cp.async.cg.shared.global [%0], [%1], 16;" :: "r"(dst), "l"(src));
}
#define CPA_COMMIT() asm volatile("cp.async.commit_group;" ::: "memory")
#define CPA_WAIT(n)  asm volatile("cp.async.wait_group %0;" :: "n"(n) : "memory")

__device__ __forceinline__ uint32_t bfpack(__nv_bfloat16 a, __nv_bfloat16 b) {
    __nv_bfloat162 t = __halves2bfloat162(a, b);
    return *reinterpret_cast<uint32_t*>(&t);
}
__device__ __forceinline__ void bsplit(float x, __nv_bfloat16& h, __nv_bfloat16& l) {
    h = __float2bfloat16(x);
    l = __float2bfloat16(x - __bfloat162float(h));
}
// split pair -> hi uint32, lo uint32
__device__ __forceinline__ void bsplit2(float a, float b, uint32_t& hi, uint32_t& lo) {
    __nv_bfloat16 ha, la, hb, lb;
    bsplit(a, ha, la); bsplit(b, hb, lb);
    hi = bfpack(ha, hb); lo = bfpack(la, lb);
}

// =============================== prep kernels ===============================
// wqkv [128 k][3072 n] -> wqkvt hi/lo [3072 n][128 k], rowbytes 256, swizzled
__global__ void prep_wqkv(const float* __restrict__ wq) {
    int idx = blockIdx.x*256 + threadIdx.x;          // 196608
    int n = idx >> 6, kp = (idx & 63) << 1;
    float a = wq[kp*3072 + n], b = wq[(kp+1)*3072 + n];
    uint32_t hi, lo; bsplit2(a, b, hi, lo);
    uint32_t off = (uint32_t)(n*256 + (((kp>>3) ^ (n&7))<<4) + (kp&7)*2);
    *(uint32_t*)((char*)g_wqh + off) = hi;
    *(uint32_t*)((char*)g_wql + off) = lo;
}
// wp [1024 k][128 d] -> wpt hi/lo [128 d][1024 k], rowbytes 2048, swizzled
__global__ void prep_wp(const float* __restrict__ wp) {
    int idx = blockIdx.x*256 + threadIdx.x;          // 65536
    int d = idx >> 9, kp = (idx & 511) << 1;
    float a = wp[kp*128 + d], b = wp[(kp+1)*128 + d];
    uint32_t hi, lo; bsplit2(a, b, hi, lo);
    uint32_t off = (uint32_t)(d*2048 + (((kp>>3) ^ (d&7))<<4) + (kp&7)*2);
    *(uint32_t*)((char*)g_wph + off) = hi;
    *(uint32_t*)((char*)g_wpl + off) = lo;
}

// =============================== LayerNorm -> split/swizzled xn ===============================
__global__ void ln_kernel(const float* __restrict__ x,
                          const float* __restrict__ w,
                          const float* __restrict__ b) {
    int row = blockIdx.x, t = threadIdx.x;
    float v = x[row*EMB + t];
    float s = v;
    #pragma unroll
    for (int o = 16; o; o >>= 1) s += __shfl_xor_sync(0xffffffffu, s, o);
    __shared__ float r1[4], r2[4];
    if ((t & 31) == 0) r1[t >> 5] = s;
    __syncthreads();
    float mean = (r1[0] + r1[1] + r1[2] + r1[3]) * (1.0f/EMB);
    float d = v - mean;
    float q = d * d;
    #pragma unroll
    for (int o = 16; o; o >>= 1) q += __shfl_xor_sync(0xffffffffu, q, o);
    if ((t & 31) == 0) r2[t >> 5] = q;
    __syncthreads();
    float var = (r2[0] + r2[1] + r2[2] + r2[3]) * (1.0f/EMB);
    float xn = d * rsqrtf(var + 1e-5f) * w[t] + b[t];
    float xn1 = __shfl_down_sync(0xffffffffu, xn, 1);
    if (!(t & 1)) {
        uint32_t hi, lo; bsplit2(xn, xn1, hi, lo);
        int rt = row >> 7, rl = row & 127;
        uint32_t off = (uint32_t)(rt*32768 + rl*256 + (((t>>3) ^ (rl&7))<<4) + (t&7)*2);
        *(uint32_t*)((char*)g_xnh + off) = hi;
        *(uint32_t*)((char*)g_xnl + off) = lo;
    }
}

// =============================== QKV GEMM (mma.sync) ===============================
// grid (48 coltiles, 128 rowtiles), 256 thr. CTA: 128 rows x 64 cols, k=128.
// Epilogue scatters into Q (scale folded) / K / Vt pre-swizzled tile stores.
#define QKV_SMEM 98304
__global__ void __launch_bounds__(256) qkv_mma(const float* __restrict__ scale) {
    extern __shared__ char smc[];
    uint32_t sb = smem_u32(smc);
    int tid = threadIdx.x, w = tid >> 5, L = tid & 31;
    int rowbase = blockIdx.y * 128;
    int colbase = blockIdx.x * 64;

    { // copies: A hi/lo 32KB each, B hi/lo 16KB each (all pre-swizzled, linear)
        const char* axh = (const char*)g_xnh + (size_t)blockIdx.y*32768;
        const char* axl = (const char*)g_xnl + (size_t)blockIdx.y*32768;
        const char* bxh = (const char*)g_wqh + (size_t)colbase*256;
        const char* bxl = (const char*)g_wql + (size_t)colbase*256;
        #pragma unroll
        for (int it = 0; it < 8; it++) {
            uint32_t o = (uint32_t)(it*256 + tid)*16;
            cpa16(sb + o,         axh + o);
            cpa16(sb + 32768 + o, axl + o);
        }
        #pragma unroll
        for (int it = 0; it < 4; it++) {
            uint32_t o = (uint32_t)(it*256 + tid)*16;
            cpa16(sb + 65536 + o, bxh + o);
            cpa16(sb + 81920 + o, bxl + o);
        }
        CPA_COMMIT(); CPA_WAIT(0);
    }
    __syncthreads();

    int l7 = L & 7;
    int rowA = (w << 4) + ((L >> 3) & 1)*8 + l7;
    int cA = L >> 4;
    uint32_t aBH = sb + rowA*256, aBL = sb + 32768 + rowA*256;
    int rB = (L & 7) + ((L >> 4) & 1)*8;     // B x4 row-within-pair
    int csel = (L >> 3) & 1;

    float acc[8][4] = {};
    #pragma unroll
    for (int kc = 0; kc < 8; kc++) {
        uint32_t ah[4], al[4];
        uint32_t ap = (uint32_t)(((kc*2 + cA) ^ l7) << 4);
        ldsm4(ah, aBH + ap);  ldsm4(al, aBL + ap);
        uint32_t cp = (uint32_t)(((kc*2 + csel) ^ l7) << 4);
        #pragma unroll
        for (int nbp = 0; nbp < 4; nbp++) {
            uint32_t bh4[4], bl4[4];
            uint32_t bo = (uint32_t)((nbp*16 + rB)*256) + cp;
            ldsm4(bh4, sb + 65536 + bo);
            ldsm4(bl4, sb + 81920 + bo);
            mma16816(acc[2*nbp],   ah, bh4);     mma16816(acc[2*nbp],   ah, bl4);
            mma16816(acc[2*nbp],   al, bh4);
            mma16816(acc[2*nbp+1], ah, bh4+2);   mma16816(acc[2*nbp+1], ah, bl4+2);
            mma16816(acc[2*nbp+1], al, bh4+2);
        }
    }

    int g = L >> 2, t2 = (L & 3)*2;
    int r0 = (w << 4) + g, r1 = r0 + 8;
    int section = colbase >> 10, h = (colbase & 1023) >> 7, dbase = colbase & 127;
    int b = rowbase >> 10, n0 = rowbase & 1023;
    int bh = b*HEADS + h;

    if (section == 0) {
        float sc = scale[h];
        char* dh = (char*)g_qh + (size_t)(bh*8 + (n0 >> 7))*32768;
        char* dl = (char*)g_ql + (size_t)(bh*8 + (n0 >> 7))*32768;
        #pragma unroll
        for (int nb = 0; nb < 8; nb++) {
            int c16 = (dbase + nb*8 + t2) >> 3;
            uint32_t hi, lo;
            uint32_t o0 = (uint32_t)(r0*256 + ((c16 ^ (r0&7))<<4) + t2*2);
            bsplit2(acc[nb][0]*sc, acc[nb][1]*sc, hi, lo);
            *(uint32_t*)(dh + o0) = hi;  *(uint32_t*)(dl + o0) = lo;
            uint32_t o1 = (uint32_t)(r1*256 + ((c16 ^ (r1&7))<<4) + t2*2);
            bsplit2(acc[nb][2]*sc, acc[nb][3]*sc, hi, lo);
            *(uint32_t*)(dh + o1) = hi;  *(uint32_t*)(dl + o1) = lo;
        }
    } else if (section == 1) {
        char* dh = (char*)g_kh + (size_t)(bh*16 + (n0 >> 6))*16384;
        char* dl = (char*)g_kl + (size_t)(bh*16 + (n0 >> 6))*16384;
        int t0 = (r0 >> 6)*16384, rl0 = r0 & 63;
        int t1 = (r1 >> 6)*16384, rl1 = r1 & 63;
        #pragma unroll
        for (int nb = 0; nb < 8; nb++) {
            int c16 = (dbase + nb*8 + t2) >> 3;
            uint32_t hi, lo;
            uint32_t o0 = (uint32_t)(t0 + rl0*256 + ((c16 ^ (rl0&7))<<4) + t2*2);
            bsplit2(acc[nb][0], acc[nb][1], hi, lo);
            *(uint32_t*)(dh + o0) = hi;  *(uint32_t*)(dl + o0) = lo;
            uint32_t o1 = (uint32_t)(t1 + rl1*256 + ((c16 ^ (rl1&7))<<4) + t2*2);
            bsplit2(acc[nb][2], acc[nb][3], hi, lo);
            *(uint32_t*)(dh + o1) = hi;  *(uint32_t*)(dl + o1) = lo;
        }
    } else {
        // V: transpose via smem stage (reuse A region), then pre-swizzled Vt stores
        __syncthreads();
        float* stg = (float*)smc;                       // [128 s][68]
        #pragma unroll
        for (int nb = 0; nb < 8; nb++) {
            int dl0 = nb*8 + t2;
            stg[r0*68 + dl0] = acc[nb][0];  stg[r0*68 + dl0 + 1] = acc[nb][1];
            stg[r1*68 + dl0] = acc[nb][2];  stg[r1*68 + dl0 + 1] = acc[nb][3];
        }
        __syncthreads();
        char* vh = (char*)g_vth + (size_t)(bh*16 + (n0 >> 6))*16384;
        char* vl = (char*)g_vtl + (size_t)(bh*16 + (n0 >> 6))*16384;
        #pragma unroll
        for (int it = 0; it < 4; it++) {
            int e = it*256 + tid, dloc = e & 63, c8 = e >> 6;     // c8 0..15 over 128 s
            uint32_t hi4[4], lo4[4];
            #pragma unroll
            for (int p = 0; p < 4; p++)
                bsplit2(stg[(c8*8 + 2*p)*68 + dloc], stg[(c8*8 + 2*p + 1)*68 + dloc],
                        hi4[p], lo4[p]);
            int d = dbase + dloc;
            uint32_t off = (uint32_t)((c8 >> 3)*16384 + d*128 + (((c8 & 7) ^ (d&7))<<4));
            *(uint4*)(vh + off) = make_uint4(hi4[0], hi4[1], hi4[2], hi4[3]);
            *(uint4*)(vl + off) = make_uint4(lo4[0], lo4[1], lo4[2], lo4[3]);
        }
    }
}

// ====================== mma.sync flash attention (pure compute) ======================
// grid (8 qt, 128 bh), 256 thr. Q resident; KV double-buffered cp.async prefetch.
#define AQ_H 0
#define AQ_L 32768
#define ABUF(b) (65536 + (b)*65536)     /* kh, kl, vth, vtl : 16KB each */
#define SMEM_ATTN 196608
__global__ void __launch_bounds__(256, 1) attn_mma() {
    extern __shared__ char smc[];
    uint32_t sb = smem_u32(smc);
    int tid = threadIdx.x, w = tid >> 5, L = tid & 31;
    int qt = blockIdx.x, bh = blockIdx.y;
    int qbase = qt * 128;

    // initial: Q tiles + KV j=0
    {
        const char* qh = (const char*)g_qh + (size_t)(bh*8 + qt)*32768;
        const char* ql = (const char*)g_ql + (size_t)(bh*8 + qt)*32768;
        #pragma unroll
        for (int it = 0; it < 8; it++) {
            uint32_t o = (uint32_t)(it*256 + tid)*16;
            cpa16(sb + AQ_H + o, qh + o);
            cpa16(sb + AQ_L + o, ql + o);
        }
        const char* kh = (const char*)g_kh + (size_t)(bh*16)*16384;
        const char* kl = (const char*)g_kl + (size_t)(bh*16)*16384;
        const char* vh = (const char*)g_vth + (size_t)(bh*16)*16384;
        const char* vl = (const char*)g_vtl + (size_t)(bh*16)*16384;
        uint32_t dst = sb + ABUF(0);
        #pragma unroll
        for (int it = 0; it < 4; it++) {
            uint32_t o = (uint32_t)(it*256 + tid)*16;
            cpa16(dst + o,         kh + o);
            cpa16(dst + 16384 + o, kl + o);
            cpa16(dst + 32768 + o, vh + o);
            cpa16(dst + 49152 + o, vl + o);
        }
        CPA_COMMIT();
    }

    int l7 = L & 7;
    int rowA = (w << 4) + ((L >> 3) & 1)*8 + l7;
    int cA = L >> 4;
    uint32_t aBH = sb + AQ_H + rowA*256, aBL = sb + AQ_L + rowA*256;
    int rB = (L & 7) + ((L >> 4) & 1)*8;
    int csel = (L >> 3) & 1;
    int g = L >> 2, t2 = (L & 3)*2;
    int rg0 = qbase + (w << 4) + g, rg1 = rg0 + 8;

    float m0 = -FLTMAX, m1 = -FLTMAX, ls0 = 0.f, ls1 = 0.f;
    float O[16][4];
    #pragma unroll
    for (int nb = 0; nb < 16; nb++) { O[nb][0]=0.f; O[nb][1]=0.f; O[nb][2]=0.f; O[nb][3]=0.f; }

    #pragma unroll 1
    for (int j = 0; j < 16; j++) {
        if (j < 15) {   // prefetch next KV
            int jn = j + 1;
            const char* kh = (const char*)g_kh + (size_t)(bh*16 + jn)*16384;
            const char* kl = (const char*)g_kl + (size_t)(bh*16 + jn)*16384;
            const char* vh = (const char*)g_vth + (size_t)(bh*16 + jn)*16384;
            const char* vl = (const char*)g_vtl + (size_t)(bh*16 + jn)*16384;
            uint32_t dst = sb + ABUF(jn & 1);
            #pragma unroll
            for (int it = 0; it < 4; it++) {
                uint32_t o = (uint32_t)(it*256 + tid)*16;
                cpa16(dst + o,         kh + o);
                cpa16(dst + 16384 + o, kl + o);
                cpa16(dst + 32768 + o, vh + o);
                cpa16(dst + 49152 + o, vl + o);
            }
            CPA_COMMIT(); CPA_WAIT(1);
        } else {
            CPA_WAIT(0);
        }
        __syncthreads();
        uint32_t kbH = sb + ABUF(j & 1), kbL = kbH + 16384;
        uint32_t vbH = kbH + 32768,      vbL = kbH + 49152;

        // ---- S = Q K^T : m16 x n64 per warp, k=128 (3-term split) ----
        float S[8][4];
        #pragma unroll
        for (int nb = 0; nb < 8; nb++) { S[nb][0]=0.f; S[nb][1]=0.f; S[nb][2]=0.f; S[nb][3]=0.f; }
        #pragma unroll
        for (int kc = 0; kc < 8; kc++) {
            uint32_t ah[4], al[4];
            uint32_t ap = (uint32_t)(((kc*2 + cA) ^ l7) << 4);
            ldsm4(ah, aBH + ap);  ldsm4(al, aBL + ap);
            uint32_t cp = (uint32_t)(((kc*2 + csel) ^ l7) << 4);
            #pragma unroll
            for (int nbp = 0; nbp < 4; nbp++) {
                uint32_t bh4[4], bl4[4];
                uint32_t bo = (uint32_t)((nbp*16 + rB)*256) + cp;
                ldsm4(bh4, kbH + bo);  ldsm4(bl4, kbL + bo);
                mma16816(S[2*nbp],   ah, bh4);    mma16816(S[2*nbp],   ah, bl4);
                mma16816(S[2*nbp],   al, bh4);
                mma16816(S[2*nbp+1], ah, bh4+2);  mma16816(S[2*nbp+1], ah, bl4+2);
                mma16816(S[2*nbp+1], al, bh4+2);
            }
        }

        // ---- diagonal mask ----
        if ((j >> 1) == qt) {
            int colbase = j*64;
            #pragma unroll
            for (int nb = 0; nb < 8; nb++) {
                int c0 = colbase + nb*8 + t2;
                if (c0     == rg0) S[nb][0] = -FLTMAX;
                if (c0 + 1 == rg0) S[nb][1] = -FLTMAX;
                if (c0     == rg1) S[nb][2] = -FLTMAX;
                if (c0 + 1 == rg1) S[nb][3] = -FLTMAX;
            }
        }

        // ---- online softmax ----
        float rmax0 = -FLTMAX, rmax1 = -FLTMAX;
        #pragma unroll
        for (int nb = 0; nb < 8; nb++) {
            rmax0 = fmaxf(rmax0, fmaxf(S[nb][0], S[nb][1]));
            rmax1 = fmaxf(rmax1, fmaxf(S[nb][2], S[nb][3]));
        }
        rmax0 = fmaxf(rmax0, __shfl_xor_sync(0xffffffffu, rmax0, 1));
        rmax0 = fmaxf(rmax0, __shfl_xor_sync(0xffffffffu, rmax0, 2));
        rmax1 = fmaxf(rmax1, __shfl_xor_sync(0xffffffffu, rmax1, 1));
        rmax1 = fmaxf(rmax1, __shfl_xor_sync(0xffffffffu, rmax1, 2));
        float mn0 = fmaxf(m0, rmax0), mn1 = fmaxf(m1, rmax1);
        float cr0 = __expf(m0 - mn0), cr1 = __expf(m1 - mn1);
        m0 = mn0; m1 = mn1;
        float rs0 = 0.f, rs1 = 0.f;
        #pragma unroll
        for (int nb = 0; nb < 8; nb++) {
            S[nb][0] = __expf(S[nb][0] - mn0); rs0 += S[nb][0];
            S[nb][1] = __expf(S[nb][1] - mn0); rs0 += S[nb][1];
            S[nb][2] = __expf(S[nb][2] - mn1); rs1 += S[nb][2];
            S[nb][3] = __expf(S[nb][3] - mn1); rs1 += S[nb][3];
        }
        rs0 += __shfl_xor_sync(0xffffffffu, rs0, 1);
        rs0 += __shfl_xor_sync(0xffffffffu, rs0, 2);
        rs1 += __shfl_xor_sync(0xffffffffu, rs1, 1);
        rs1 += __shfl_xor_sync(0xffffffffu, rs1, 2);
        ls0 = ls0*cr0 + rs0;
        ls1 = ls1*cr1 + rs1;
        #pragma unroll
        for (int nb = 0; nb < 16; nb++) {
            O[nb][0] *= cr0;  O[nb][1] *= cr0;
            O[nb][2] *= cr1;  O[nb][3] *= cr1;
        }

        // ---- O += P V (P regs -> A frags; B from Vt, rowbytes 128) ----
        #pragma unroll
        for (int kc = 0; kc < 4; kc++) {
            uint32_t ah[4], al[4];
            bsplit2(S[2*kc][0],   S[2*kc][1],   ah[0], al[0]);
            bsplit2(S[2*kc][2],   S[2*kc][3],   ah[1], al[1]);
            bsplit2(S[2*kc+1][0], S[2*kc+1][1], ah[2], al[2]);
            bsplit2(S[2*kc+1][2], S[2*kc+1][3], ah[3], al[3]);
            uint32_t cp = (uint32_t)(((kc*2 + csel) ^ l7) << 4);
            #pragma unroll
            for (int nbp = 0; nbp < 8; nbp++) {
                uint32_t bh4[4], bl4[4];
                uint32_t bo = (uint32_t)((nbp*16 + rB)*128) + cp;
                ldsm4(bh4, vbH + bo);  ldsm4(bl4, vbL + bo);
                mma16816(O[2*nbp],   ah, bh4);    mma16816(O[2*nbp],   ah, bl4);
                mma16816(O[2*nbp],   al, bh4);
                mma16816(O[2*nbp+1], ah, bh4+2);  mma16816(O[2*nbp+1], ah, bl4+2);
                mma16816(O[2*nbp+1], al, bh4+2);
            }
        }
        __syncthreads();   // all warps done with this buffer before it is re-filled
    }

    // ---- epilogue: normalize, split, write pre-swizzled O tiles for proj ----
    float inv0 = 1.0f / ls0, inv1 = 1.0f / ls1;
    int bb = bh >> 3, h = bh & 7;
    int rowtile = bb*8 + qt;
    int rl0 = (w << 4) + g, rl1 = rl0 + 8;
    char* aoh = (char*)g_aoh + (size_t)rowtile*262144;
    char* aol = (char*)g_aol + (size_t)rowtile*262144;
    #pragma unroll
    for (int nb = 0; nb < 16; nb++) {
        int c16 = h*16 + nb;
        uint32_t hi, lo;
        uint32_t o0 = (uint32_t)(rl0*2048 + ((c16 ^ (rl0&7))<<4) + t2*2);
        bsplit2(O[nb][0]*inv0, O[nb][1]*inv0, hi, lo);
        *(uint32_t*)(aoh + o0) = hi;  *(uint32_t*)(aol + o0) = lo;
        uint32_t o1 = (uint32_t)(rl1*2048 + ((c16 ^ (rl1&7))<<4) + t2*2);
        bsplit2(O[nb][2]*inv1, O[nb][3]*inv1, hi, lo);
        *(uint32_t*)(aoh + o1) = hi;  *(uint32_t*)(aol + o1) = lo;
    }
}

// =============================== Output projection (mma.sync) ===============================
// grid 128 rowtiles, 256 thr. CTA: 128 rows x 128 cols, k=1024 in 8 chunks of 128.
#define PROJ_SMEM 131072
__global__ void __launch_bounds__(256, 1) proj_mma(const float* __restrict__ bias,
                                                   float* __restrict__ out) {
    extern __shared__ char smc[];
    uint32_t sb = smem_u32(smc);
    int tid = threadIdx.x, w = tid >> 5, L = tid & 31;
    int rowtile = blockIdx.x;
    const char* aoh = (const char*)g_aoh + (size_t)rowtile*262144;
    const char* aol = (const char*)g_aol + (size_t)rowtile*262144;

    int l7 = L & 7;
    int rowA = (w << 4) + ((L >> 3) & 1)*8 + l7;
    int cA = L >> 4;
    int rB = (L & 7) + ((L >> 4) & 1)*8;
    int csel = (L >> 3) & 1;
    int g = L >> 2, t2 = (L & 3)*2;

    float acc[16][4];
    #pragma unroll
    for (int nb = 0; nb < 16; nb++) { acc[nb][0]=0.f; acc[nb][1]=0.f; acc[nb][2]=0.f; acc[nb][3]=0.f; }

    #pragma unroll 1
    for (int kb = 0; kb < 8; kb++) {
        __syncthreads();
        // copy k-chunk: A hi/lo [128][256B] + B hi/lo [128][256B]
        #pragma unroll
        for (int it = 0; it < 8; it++) {
            int e = it*256 + tid, r = e >> 4, jj = e & 15;
            uint32_t go = (uint32_t)(r*2048 + kb*256 + jj*16);
            uint32_t so = (uint32_t)(r*256 + jj*16);
            cpa16(sb + so,          aoh + go);
            cpa16(sb + 32768 + so,  aol + go);
            cpa16(sb + 65536 + so,  (const char*)g_wph + go);
            cpa16(sb + 98304 + so,  (const char*)g_wpl + go);
        }
        CPA_COMMIT(); CPA_WAIT(0);
        __syncthreads();

        #pragma unroll
        for (int kc = 0; kc < 8; kc++) {
            uint32_t ah[4], al[4];
            uint32_t ap = (uint32_t)(rowA*256 + (((kc*2 + cA) ^ l7) << 4));
            ldsm4(ah, sb + ap);  ldsm4(al, sb + 32768 + ap);
            uint32_t cp = (uint32_t)(((kc*2 + csel) ^ l7) << 4);
            #pragma unroll
            for (int nbp = 0; nbp < 8; nbp++) {
                uint32_t bh4[4], bl4[4];
                uint32_t bo = (uint32_t)((nbp*16 + rB)*256) + cp;
                ldsm4(bh4, sb + 65536 + bo);  ldsm4(bl4, sb + 98304 + bo);
                mma16816(acc[2*nbp],   ah, bh4);    mma16816(acc[2*nbp],   ah, bl4);
                mma16816(acc[2*nbp],   al, bh4);
                mma16816(acc[2*nbp+1], ah, bh4+2);  mma16816(acc[2*nbp+1], ah, bl4+2);
                mma16816(acc[2*nbp+1], al, bh4+2);
            }
        }
    }

    int r0 = rowtile*128 + (w << 4) + g, r1 = r0 + 8;
    #pragma unroll
    for (int nb = 0; nb < 16; nb++) {
        int col = nb*8 + t2;
        float b0 = bias[col], b1 = bias[col + 1];
        *(float2*)&out[r0*128 + col] = make_float2(acc[nb][0] + b0, acc[nb][1] + b1);
        *(float2*)&out[r1*128 + col] = make_float2(acc[nb][2] + b0, acc[nb][3] + b1);
    }
}

// =============================== launch ===============================
extern "C" void kernel_launch(void* const* d_in, const int* in_sizes, int n_in,
                              void* d_out, int out_size) {
    const float* x      = (const float*)d_in[0];
    const float* ln_w   = (const float*)d_in[1];
    const float* ln_b   = (const float*)d_in[2];
    const float* w_qkv  = (const float*)d_in[3];
    const float* scale  = (const float*)d_in[4];
    const float* w_proj = (const float*)d_in[5];
    const float* b_proj = (const float*)d_in[6];
    float* out = (float*)d_out;

    cudaFuncSetAttribute(qkv_mma,  cudaFuncAttributeMaxDynamicSharedMemorySize, QKV_SMEM);
    cudaFuncSetAttribute(attn_mma, cudaFuncAttributeMaxDynamicSharedMemorySize, SMEM_ATTN);
    cudaFuncSetAttribute(proj_mma, cudaFuncAttributeMaxDynamicSharedMemorySize, PROJ_SMEM);

    prep_wqkv<<<768, 256>>>(w_qkv);
    prep_wp  <<<256, 256>>>(w_proj);
    ln_kernel<<<ROWS_TOT, EMB>>>(x, ln_w, ln_b);
    qkv_mma  <<<dim3(48, 128), 256, QKV_SMEM>>>(scale);
    attn_mma <<<dim3(8, 128), 256, SMEM_ATTN>>>();
    proj_mma <<<128, 256, PROJ_SMEM>>>(b_proj, out);
}

// round 12
// speedup vs baseline: 4.6783x; 1.0316x over previous
#include <cuda_runtime.h>
#include <cuda_bf16.h>
#include <cstdint>

#define BATCH  16
#define NPAT   1024
#define EMB    128
#define HEADS  8
#define ROWS_TOT (BATCH*NPAT)      /* 16384 */
#define INNERD   (EMB*HEADS)       /* 1024  */
#define FLTMAX 3.402823466e38f

// ---------------- scratch (static device allocations; allowed) ----------------
// All bf16 tile stores are PRE-SWIZZLED in the exact smem layout the consumers use,
// so every consumer copy is a linear 16B cp.async.
__device__ uint4 g_xnh[4194304/16],  g_xnl[4194304/16];    // xn  [128 rt][128r][128d]
__device__ uint4 g_qh [33554432/16], g_ql [33554432/16];   // Q   [128 bh][8 qt][128][128d]
__device__ uint4 g_kh [33554432/16], g_kl [33554432/16];   // K   [128 bh][16 jt][64][128d]
__device__ uint4 g_vth[33554432/16], g_vtl[33554432/16];   // Vt  [128 bh][16 jt][128d][64s]
__device__ uint4 g_aoh[33554432/16], g_aol[33554432/16];   // O   [128 rt][128r][1024k]
__device__ uint4 g_wqh[786432/16],   g_wql[786432/16];     // wqkv^T [3072 n][128 k]
__device__ uint4 g_wph[262144/16],   g_wpl[262144/16];     // wproj^T [128 d][1024 k]

// ====================== PTX helpers ======================
__device__ __forceinline__ uint32_t smem_u32(const void* p) {
    uint32_t a;
    asm("{ .reg .u64 t; cvta.to.shared.u64 t, %1; cvt.u32.u64 %0, t; }" : "=r"(a) : "l"(p));
    return a;
}
__device__ __forceinline__ void ldsm4(uint32_t* r, uint32_t a) {
    asm volatile("ldmatrix.sync.aligned.m8n8.x4.shared.b16 {%0,%1,%2,%3}, [%4];"
        : "=r"(r[0]), "=r"(r[1]), "=r"(r[2]), "=r"(r[3]) : "r"(a));
}
__device__ __forceinline__ void mma16816(float* d, const uint32_t* a, const uint32_t* b) {
    asm volatile("mma.sync.aligned.m16n8k16.row.col.f32.bf16.bf16.f32 "
        "{%0,%1,%2,%3}, {%4,%5,%6,%7}, {%8,%9}, {%0,%1,%2,%3};"
        : "+f"(d[0]), "+f"(d[1]), "+f"(d[2]), "+f"(d[3])
        : "r"(a[0]), "r"(a[1]), "r"(a[2]), "r"(a[3]), "r"(b[0]), "r"(b[1]));
}
__device__ __forceinline__ void cpa16(uint32_t dst, const void* src) {
    asm volatile("cp.async.cg.shared.global [%0], [%1], 16;" :: "r"(dst), "l"(src));
}
#define CPA_COMMIT() asm volatile("cp.async.commit_group;" ::: "memory")
#define CPA_WAIT(n)  asm volatile("cp.async.wait_group %0;" :: "n"(n) : "memory")

__device__ __forceinline__ uint32_t bfpack(__nv_bfloat16 a, __nv_bfloat16 b) {
    __nv_bfloat162 t = __halves2bfloat162(a, b);
    return *reinterpret_cast<uint32_t*>(&t);
}
__device__ __forceinline__ void bsplit(float x, __nv_bfloat16& h, __nv_bfloat16& l) {
    h = __float2bfloat16(x);
    l = __float2bfloat16(x - __bfloat162float(h));
}
__device__ __forceinline__ void bsplit2(float a, float b, uint32_t& hi, uint32_t& lo) {
    __nv_bfloat16 ha, la, hb, lb;
    bsplit(a, ha, la); bsplit(b, hb, lb);
    hi = bfpack(ha, hb); lo = bfpack(la, lb);
}

// =============================== prep kernels ===============================
__global__ void prep_wqkv(const float* __restrict__ wq) {
    int idx = blockIdx.x*256 + threadIdx.x;          // 196608
    int n = idx >> 6, kp = (idx & 63) << 1;
    float a = wq[kp*3072 + n], b = wq[(kp+1)*3072 + n];
    uint32_t hi, lo; bsplit2(a, b, hi, lo);
    uint32_t off = (uint32_t)(n*256 + (((kp>>3) ^ (n&7))<<4) + (kp&7)*2);
    *(uint32_t*)((char*)g_wqh + off) = hi;
    *(uint32_t*)((char*)g_wql + off) = lo;
}
__global__ void prep_wp(const float* __restrict__ wp) {
    int idx = blockIdx.x*256 + threadIdx.x;          // 65536
    int d = idx >> 9, kp = (idx & 511) << 1;
    float a = wp[kp*128 + d], b = wp[(kp+1)*128 + d];
    uint32_t hi, lo; bsplit2(a, b, hi, lo);
    uint32_t off = (uint32_t)(d*2048 + (((kp>>3) ^ (d&7))<<4) + (kp&7)*2);
    *(uint32_t*)((char*)g_wph + off) = hi;
    *(uint32_t*)((char*)g_wpl + off) = lo;
}

// =============================== LayerNorm (warp-per-row) ===============================
// grid 2048, block 256 (8 warps = 8 rows). float4 per lane.
__global__ void __launch_bounds__(256) ln_kernel(const float* __restrict__ x,
                                                 const float* __restrict__ w,
                                                 const float* __restrict__ b) {
    int wid = threadIdx.x >> 5, lane = threadIdx.x & 31;
    int row = blockIdx.x*8 + wid;
    float4 v = *(const float4*)&x[row*EMB + lane*4];
    float s = v.x + v.y + v.z + v.w;
    #pragma unroll
    for (int o = 16; o; o >>= 1) s += __shfl_xor_sync(0xffffffffu, s, o);
    float mean = s * (1.0f/EMB);
    float d0 = v.x - mean, d1 = v.y - mean, d2 = v.z - mean, d3 = v.w - mean;
    float q = d0*d0 + d1*d1 + d2*d2 + d3*d3;
    #pragma unroll
    for (int o = 16; o; o >>= 1) q += __shfl_xor_sync(0xffffffffu, q, o);
    float rinv = rsqrtf(q * (1.0f/EMB) + 1e-5f);
    float4 wv = *(const float4*)&w[lane*4];
    float4 bv = *(const float4*)&b[lane*4];
    float xn0 = d0*rinv*wv.x + bv.x, xn1 = d1*rinv*wv.y + bv.y;
    float xn2 = d2*rinv*wv.z + bv.z, xn3 = d3*rinv*wv.w + bv.w;
    uint32_t h0, l0, h1, l1;
    bsplit2(xn0, xn1, h0, l0);
    bsplit2(xn2, xn3, h1, l1);
    int rt = row >> 7, rl = row & 127, dd = lane*4;
    uint32_t off = (uint32_t)(rt*32768 + rl*256 + (((dd>>3) ^ (rl&7))<<4) + (dd&7)*2);
    *(uint2*)((char*)g_xnh + off) = make_uint2(h0, h1);
    *(uint2*)((char*)g_xnl + off) = make_uint2(l0, l1);
}

// =============================== QKV GEMM (mma.sync, 2 CTA/SM) ===============================
#define QKV_SMEM 98304
__global__ void __launch_bounds__(256, 2) qkv_mma(const float* __restrict__ scale) {
    extern __shared__ char smc[];
    uint32_t sb = smem_u32(smc);
    int tid = threadIdx.x, w = tid >> 5, L = tid & 31;
    int rowbase = blockIdx.y * 128;
    int colbase = blockIdx.x * 64;

    { // copies: A hi/lo 32KB each, B hi/lo 16KB each (pre-swizzled, linear)
        const char* axh = (const char*)g_xnh + (size_t)blockIdx.y*32768;
        const char* axl = (const char*)g_xnl + (size_t)blockIdx.y*32768;
        const char* bxh = (const char*)g_wqh + (size_t)colbase*256;
        const char* bxl = (const char*)g_wql + (size_t)colbase*256;
        #pragma unroll
        for (int it = 0; it < 8; it++) {
            uint32_t o = (uint32_t)(it*256 + tid)*16;
            cpa16(sb + o,         axh + o);
            cpa16(sb + 32768 + o, axl + o);
        }
        #pragma unroll
        for (int it = 0; it < 4; it++) {
            uint32_t o = (uint32_t)(it*256 + tid)*16;
            cpa16(sb + 65536 + o, bxh + o);
            cpa16(sb + 81920 + o, bxl + o);
        }
        CPA_COMMIT(); CPA_WAIT(0);
    }
    __syncthreads();

    int l7 = L & 7;
    int rowA = (w << 4) + ((L >> 3) & 1)*8 + l7;
    int cA = L >> 4;
    uint32_t aBH = sb + rowA*256, aBL = sb + 32768 + rowA*256;
    int rB = (L & 7) + ((L >> 4) & 1)*8;
    int csel = (L >> 3) & 1;

    float acc[8][4] = {};
    #pragma unroll
    for (int kc = 0; kc < 8; kc++) {
        uint32_t ah[4], al[4];
        uint32_t ap = (uint32_t)(((kc*2 + cA) ^ l7) << 4);
        ldsm4(ah, aBH + ap);  ldsm4(al, aBL + ap);
        uint32_t cp = (uint32_t)(((kc*2 + csel) ^ l7) << 4);
        #pragma unroll
        for (int nbp = 0; nbp < 4; nbp++) {
            uint32_t bh4[4], bl4[4];
            uint32_t bo = (uint32_t)((nbp*16 + rB)*256) + cp;
            ldsm4(bh4, sb + 65536 + bo);
            ldsm4(bl4, sb + 81920 + bo);
            mma16816(acc[2*nbp],   ah, bh4);     mma16816(acc[2*nbp],   ah, bl4);
            mma16816(acc[2*nbp],   al, bh4);
            mma16816(acc[2*nbp+1], ah, bh4+2);   mma16816(acc[2*nbp+1], ah, bl4+2);
            mma16816(acc[2*nbp+1], al, bh4+2);
        }
    }

    int g = L >> 2, t2 = (L & 3)*2;
    int r0 = (w << 4) + g, r1 = r0 + 8;
    int section = colbase >> 10, h = (colbase & 1023) >> 7, dbase = colbase & 127;
    int b = rowbase >> 10, n0 = rowbase & 1023;
    int bh = b*HEADS + h;

    if (section == 0) {
        float sc = scale[h];
        char* dh = (char*)g_qh + (size_t)(bh*8 + (n0 >> 7))*32768;
        char* dl = (char*)g_ql + (size_t)(bh*8 + (n0 >> 7))*32768;
        #pragma unroll
        for (int nb = 0; nb < 8; nb++) {
            int c16 = (dbase + nb*8 + t2) >> 3;
            uint32_t hi, lo;
            uint32_t o0 = (uint32_t)(r0*256 + ((c16 ^ (r0&7))<<4) + t2*2);
            bsplit2(acc[nb][0]*sc, acc[nb][1]*sc, hi, lo);
            *(uint32_t*)(dh + o0) = hi;  *(uint32_t*)(dl + o0) = lo;
            uint32_t o1 = (uint32_t)(r1*256 + ((c16 ^ (r1&7))<<4) + t2*2);
            bsplit2(acc[nb][2]*sc, acc[nb][3]*sc, hi, lo);
            *(uint32_t*)(dh + o1) = hi;  *(uint32_t*)(dl + o1) = lo;
        }
    } else if (section == 1) {
        char* dh = (char*)g_kh + (size_t)(bh*16 + (n0 >> 6))*16384;
        char* dl = (char*)g_kl + (size_t)(bh*16 + (n0 >> 6))*16384;
        int t0 = (r0 >> 6)*16384, rl0 = r0 & 63;
        int t1 = (r1 >> 6)*16384, rl1 = r1 & 63;
        #pragma unroll
        for (int nb = 0; nb < 8; nb++) {
            int c16 = (dbase + nb*8 + t2) >> 3;
            uint32_t hi, lo;
            uint32_t o0 = (uint32_t)(t0 + rl0*256 + ((c16 ^ (rl0&7))<<4) + t2*2);
            bsplit2(acc[nb][0], acc[nb][1], hi, lo);
            *(uint32_t*)(dh + o0) = hi;  *(uint32_t*)(dl + o0) = lo;
            uint32_t o1 = (uint32_t)(t1 + rl1*256 + ((c16 ^ (rl1&7))<<4) + t2*2);
            bsplit2(acc[nb][2], acc[nb][3], hi, lo);
            *(uint32_t*)(dh + o1) = hi;  *(uint32_t*)(dl + o1) = lo;
        }
    } else {
        __syncthreads();
        float* stg = (float*)smc;                       // [128 s][68]
        #pragma unroll
        for (int nb = 0; nb < 8; nb++) {
            int dl0 = nb*8 + t2;
            stg[r0*68 + dl0] = acc[nb][0];  stg[r0*68 + dl0 + 1] = acc[nb][1];
            stg[r1*68 + dl0] = acc[nb][2];  stg[r1*68 + dl0 + 1] = acc[nb][3];
        }
        __syncthreads();
        char* vh = (char*)g_vth + (size_t)(bh*16 + (n0 >> 6))*16384;
        char* vl = (char*)g_vtl + (size_t)(bh*16 + (n0 >> 6))*16384;
        #pragma unroll
        for (int it = 0; it < 4; it++) {
            int e = it*256 + tid, dloc = e & 63, c8 = e >> 6;
            uint32_t hi4[4], lo4[4];
            #pragma unroll
            for (int p = 0; p < 4; p++)
                bsplit2(stg[(c8*8 + 2*p)*68 + dloc], stg[(c8*8 + 2*p + 1)*68 + dloc],
                        hi4[p], lo4[p]);
            int d = dbase + dloc;
            uint32_t off = (uint32_t)((c8 >> 3)*16384 + d*128 + (((c8 & 7) ^ (d&7))<<4));
            *(uint4*)(vh + off) = make_uint4(hi4[0], hi4[1], hi4[2], hi4[3]);
            *(uint4*)(vl + off) = make_uint4(lo4[0], lo4[1], lo4[2], lo4[3]);
        }
    }
}

// ====================== mma.sync flash attention (unchanged from R11) ======================
#define AQ_H 0
#define AQ_L 32768
#define ABUF(b) (65536 + (b)*65536)     /* kh, kl, vth, vtl : 16KB each */
#define SMEM_ATTN 196608
__global__ void __launch_bounds__(256, 1) attn_mma() {
    extern __shared__ char smc[];
    uint32_t sb = smem_u32(smc);
    int tid = threadIdx.x, w = tid >> 5, L = tid & 31;
    int qt = blockIdx.x, bh = blockIdx.y;
    int qbase = qt * 128;

    {
        const char* qh = (const char*)g_qh + (size_t)(bh*8 + qt)*32768;
        const char* ql = (const char*)g_ql + (size_t)(bh*8 + qt)*32768;
        #pragma unroll
        for (int it = 0; it < 8; it++) {
            uint32_t o = (uint32_t)(it*256 + tid)*16;
            cpa16(sb + AQ_H + o, qh + o);
            cpa16(sb + AQ_L + o, ql + o);
        }
        const char* kh = (const char*)g_kh + (size_t)(bh*16)*16384;
        const char* kl = (const char*)g_kl + (size_t)(bh*16)*16384;
        const char* vh = (const char*)g_vth + (size_t)(bh*16)*16384;
        const char* vl = (const char*)g_vtl + (size_t)(bh*16)*16384;
        uint32_t dst = sb + ABUF(0);
        #pragma unroll
        for (int it = 0; it < 4; it++) {
            uint32_t o = (uint32_t)(it*256 + tid)*16;
            cpa16(dst + o,         kh + o);
            cpa16(dst + 16384 + o, kl + o);
            cpa16(dst + 32768 + o, vh + o);
            cpa16(dst + 49152 + o, vl + o);
        }
        CPA_COMMIT();
    }

    int l7 = L & 7;
    int rowA = (w << 4) + ((L >> 3) & 1)*8 + l7;
    int cA = L >> 4;
    uint32_t aBH = sb + AQ_H + rowA*256, aBL = sb + AQ_L + rowA*256;
    int rB = (L & 7) + ((L >> 4) & 1)*8;
    int csel = (L >> 3) & 1;
    int g = L >> 2, t2 = (L & 3)*2;
    int rg0 = qbase + (w << 4) + g, rg1 = rg0 + 8;

    float m0 = -FLTMAX, m1 = -FLTMAX, ls0 = 0.f, ls1 = 0.f;
    float O[16][4];
    #pragma unroll
    for (int nb = 0; nb < 16; nb++) { O[nb][0]=0.f; O[nb][1]=0.f; O[nb][2]=0.f; O[nb][3]=0.f; }

    #pragma unroll 1
    for (int j = 0; j < 16; j++) {
        if (j < 15) {
            int jn = j + 1;
            const char* kh = (const char*)g_kh + (size_t)(bh*16 + jn)*16384;
            const char* kl = (const char*)g_kl + (size_t)(bh*16 + jn)*16384;
            const char* vh = (const char*)g_vth + (size_t)(bh*16 + jn)*16384;
            const char* vl = (const char*)g_vtl + (size_t)(bh*16 + jn)*16384;
            uint32_t dst = sb + ABUF(jn & 1);
            #pragma unroll
            for (int it = 0; it < 4; it++) {
                uint32_t o = (uint32_t)(it*256 + tid)*16;
                cpa16(dst + o,         kh + o);
                cpa16(dst + 16384 + o, kl + o);
                cpa16(dst + 32768 + o, vh + o);
                cpa16(dst + 49152 + o, vl + o);
            }
            CPA_COMMIT(); CPA_WAIT(1);
        } else {
            CPA_WAIT(0);
        }
        __syncthreads();
        uint32_t kbH = sb + ABUF(j & 1), kbL = kbH + 16384;
        uint32_t vbH = kbH + 32768,      vbL = kbH + 49152;

        float S[8][4];
        #pragma unroll
        for (int nb = 0; nb < 8; nb++) { S[nb][0]=0.f; S[nb][1]=0.f; S[nb][2]=0.f; S[nb][3]=0.f; }
        #pragma unroll
        for (int kc = 0; kc < 8; kc++) {
            uint32_t ah[4], al[4];
            uint32_t ap = (uint32_t)(((kc*2 + cA) ^ l7) << 4);
            ldsm4(ah, aBH + ap);  ldsm4(al, aBL + ap);
            uint32_t cp = (uint32_t)(((kc*2 + csel) ^ l7) << 4);
            #pragma unroll
            for (int nbp = 0; nbp < 4; nbp++) {
                uint32_t bh4[4], bl4[4];
                uint32_t bo = (uint32_t)((nbp*16 + rB)*256) + cp;
                ldsm4(bh4, kbH + bo);  ldsm4(bl4, kbL + bo);
                mma16816(S[2*nbp],   ah, bh4);    mma16816(S[2*nbp],   ah, bl4);
                mma16816(S[2*nbp],   al, bh4);
                mma16816(S[2*nbp+1], ah, bh4+2);  mma16816(S[2*nbp+1], ah, bl4+2);
                mma16816(S[2*nbp+1], al, bh4+2);
            }
        }

        if ((j >> 1) == qt) {
            int colbase = j*64;
            #pragma unroll
            for (int nb = 0; nb < 8; nb++) {
                int c0 = colbase + nb*8 + t2;
                if (c0     == rg0) S[nb][0] = -FLTMAX;
                if (c0 + 1 == rg0) S[nb][1] = -FLTMAX;
                if (c0     == rg1) S[nb][2] = -FLTMAX;
                if (c0 + 1 == rg1) S[nb][3] = -FLTMAX;
            }
        }

        float rmax0 = -FLTMAX, rmax1 = -FLTMAX;
        #pragma unroll
        for (int nb = 0; nb < 8; nb++) {
            rmax0 = fmaxf(rmax0, fmaxf(S[nb][0], S[nb][1]));
            rmax1 = fmaxf(rmax1, fmaxf(S[nb][2], S[nb][3]));
        }
        rmax0 = fmaxf(rmax0, __shfl_xor_sync(0xffffffffu, rmax0, 1));
        rmax0 = fmaxf(rmax0, __shfl_xor_sync(0xffffffffu, rmax0, 2));
        rmax1 = fmaxf(rmax1, __shfl_xor_sync(0xffffffffu, rmax1, 1));
        rmax1 = fmaxf(rmax1, __shfl_xor_sync(0xffffffffu, rmax1, 2));
        float mn0 = fmaxf(m0, rmax0), mn1 = fmaxf(m1, rmax1);
        float cr0 = __expf(m0 - mn0), cr1 = __expf(m1 - mn1);
        m0 = mn0; m1 = mn1;
        float rs0 = 0.f, rs1 = 0.f;
        #pragma unroll
        for (int nb = 0; nb < 8; nb++) {
            S[nb][0] = __expf(S[nb][0] - mn0); rs0 += S[nb][0];
            S[nb][1] = __expf(S[nb][1] - mn0); rs0 += S[nb][1];
            S[nb][2] = __expf(S[nb][2] - mn1); rs1 += S[nb][2];
            S[nb][3] = __expf(S[nb][3] - mn1); rs1 += S[nb][3];
        }
        rs0 += __shfl_xor_sync(0xffffffffu, rs0, 1);
        rs0 += __shfl_xor_sync(0xffffffffu, rs0, 2);
        rs1 += __shfl_xor_sync(0xffffffffu, rs1, 1);
        rs1 += __shfl_xor_sync(0xffffffffu, rs1, 2);
        ls0 = ls0*cr0 + rs0;
        ls1 = ls1*cr1 + rs1;
        #pragma unroll
        for (int nb = 0; nb < 16; nb++) {
            O[nb][0] *= cr0;  O[nb][1] *= cr0;
            O[nb][2] *= cr1;  O[nb][3] *= cr1;
        }

        #pragma unroll
        for (int kc = 0; kc < 4; kc++) {
            uint32_t ah[4], al[4];
            bsplit2(S[2*kc][0],   S[2*kc][1],   ah[0], al[0]);
            bsplit2(S[2*kc][2],   S[2*kc][3],   ah[1], al[1]);
            bsplit2(S[2*kc+1][0], S[2*kc+1][1], ah[2], al[2]);
            bsplit2(S[2*kc+1][2], S[2*kc+1][3], ah[3], al[3]);
            uint32_t cp = (uint32_t)(((kc*2 + csel) ^ l7) << 4);
            #pragma unroll
            for (int nbp = 0; nbp < 8; nbp++) {
                uint32_t bh4[4], bl4[4];
                uint32_t bo = (uint32_t)((nbp*16 + rB)*128) + cp;
                ldsm4(bh4, vbH + bo);  ldsm4(bl4, vbL + bo);
                mma16816(O[2*nbp],   ah, bh4);    mma16816(O[2*nbp],   ah, bl4);
                mma16816(O[2*nbp],   al, bh4);
                mma16816(O[2*nbp+1], ah, bh4+2);  mma16816(O[2*nbp+1], ah, bl4+2);
                mma16816(O[2*nbp+1], al, bh4+2);
            }
        }
        __syncthreads();
    }

    float inv0 = 1.0f / ls0, inv1 = 1.0f / ls1;
    int bb = bh >> 3, h = bh & 7;
    int rowtile = bb*8 + qt;
    int rl0 = (w << 4) + g, rl1 = rl0 + 8;
    char* aoh = (char*)g_aoh + (size_t)rowtile*262144;
    char* aol = (char*)g_aol + (size_t)rowtile*262144;
    #pragma unroll
    for (int nb = 0; nb < 16; nb++) {
        int c16 = h*16 + nb;
        uint32_t hi, lo;
        uint32_t o0 = (uint32_t)(rl0*2048 + ((c16 ^ (rl0&7))<<4) + t2*2);
        bsplit2(O[nb][0]*inv0, O[nb][1]*inv0, hi, lo);
        *(uint32_t*)(aoh + o0) = hi;  *(uint32_t*)(aol + o0) = lo;
        uint32_t o1 = (uint32_t)(rl1*2048 + ((c16 ^ (rl1&7))<<4) + t2*2);
        bsplit2(O[nb][2]*inv1, O[nb][3]*inv1, hi, lo);
        *(uint32_t*)(aoh + o1) = hi;  *(uint32_t*)(aol + o1) = lo;
    }
}

// =============================== Output projection (double-buffered) ===============================
// grid 128 rowtiles, 256 thr. k=1024 in 16 chunks of 64, 2-stage cp.async pipeline.
// stage s base = s*65536: AH 0, AL 16384, BH 32768, BL 49152 (each [128r][64k] = 16KB)
#define PROJ_SMEM 131072
__global__ void __launch_bounds__(256, 1) proj_mma(const float* __restrict__ bias,
                                                   float* __restrict__ out) {
    extern __shared__ char smc[];
    uint32_t sb = smem_u32(smc);
    int tid = threadIdx.x, w = tid >> 5, L = tid & 31;
    int rowtile = blockIdx.x;
    const char* aoh = (const char*)g_aoh + (size_t)rowtile*262144;
    const char* aol = (const char*)g_aol + (size_t)rowtile*262144;

    int l7 = L & 7;
    int rowA = (w << 4) + ((L >> 3) & 1)*8 + l7;
    int cA = L >> 4;
    int rB = (L & 7) + ((L >> 4) & 1)*8;
    int csel = (L >> 3) & 1;
    int g = L >> 2, t2 = (L & 3)*2;

    // prefetch chunk kb into stage st: 1024 lines each of AH/AL/BH/BL
    auto prefetch = [&](int kb, int st) {
        uint32_t base = sb + st*65536;
        #pragma unroll
        for (int it = 0; it < 4; it++) {
            int e = it*256 + tid, r = e >> 3, jj = e & 7;
            uint32_t go = (uint32_t)(r*2048 + kb*128 + ((jj ^ (r&7))<<4));
            uint32_t so = (uint32_t)(r*128 + ((jj ^ (r&7))<<4));
            cpa16(base + so,          aoh + go);
            cpa16(base + 16384 + so,  aol + go);
            cpa16(base + 32768 + so,  (const char*)g_wph + go);
            cpa16(base + 49152 + so,  (const char*)g_wpl + go);
        }
        CPA_COMMIT();
    };

    float acc[16][4];
    #pragma unroll
    for (int nb = 0; nb < 16; nb++) { acc[nb][0]=0.f; acc[nb][1]=0.f; acc[nb][2]=0.f; acc[nb][3]=0.f; }

    prefetch(0, 0);
    #pragma unroll 1
    for (int kb = 0; kb < 16; kb++) {
        if (kb < 15) { prefetch(kb + 1, (kb + 1) & 1); CPA_WAIT(1); }
        else          CPA_WAIT(0);
        __syncthreads();
        uint32_t base = sb + (kb & 1)*65536;
        uint32_t aH = base + rowA*128, aL = base + 16384 + rowA*128;
        #pragma unroll
        for (int kc = 0; kc < 4; kc++) {
            uint32_t ah[4], al[4];
            uint32_t ap = (uint32_t)(((kc*2 + cA) ^ l7) << 4);
            ldsm4(ah, aH + ap);  ldsm4(al, aL + ap);
            uint32_t cp = (uint32_t)(((kc*2 + csel) ^ l7) << 4);
            #pragma unroll
            for (int nbp = 0; nbp < 8; nbp++) {
                uint32_t bh4[4], bl4[4];
                uint32_t bo = (uint32_t)((nbp*16 + rB)*128) + cp;
                ldsm4(bh4, base + 32768 + bo);  ldsm4(bl4, base + 49152 + bo);
                mma16816(acc[2*nbp],   ah, bh4);    mma16816(acc[2*nbp],   ah, bl4);
                mma16816(acc[2*nbp],   al, bh4);
                mma16816(acc[2*nbp+1], ah, bh4+2);  mma16816(acc[2*nbp+1], ah, bl4+2);
                mma16816(acc[2*nbp+1], al, bh4+2);
            }
        }
        __syncthreads();   // stage read done before it is refilled next iter
    }

    int r0 = rowtile*128 + (w << 4) + g, r1 = r0 + 8;
    #pragma unroll
    for (int nb = 0; nb < 16; nb++) {
        int col = nb*8 + t2;
        float b0 = bias[col], b1 = bias[col + 1];
        *(float2*)&out[r0*128 + col] = make_float2(acc[nb][0] + b0, acc[nb][1] + b1);
        *(float2*)&out[r1*128 + col] = make_float2(acc[nb][2] + b0, acc[nb][3] + b1);
    }
}

// =============================== launch ===============================
extern "C" void kernel_launch(void* const* d_in, const int* in_sizes, int n_in,
                              void* d_out, int out_size) {
    const float* x      = (const float*)d_in[0];
    const float* ln_w   = (const float*)d_in[1];
    const float* ln_b   = (const float*)d_in[2];
    const float* w_qkv  = (const float*)d_in[3];
    const float* scale  = (const float*)d_in[4];
    const float* w_proj = (const float*)d_in[5];
    const float* b_proj = (const float*)d_in[6];
    float* out = (float*)d_out;

    cudaFuncSetAttribute(qkv_mma,  cudaFuncAttributeMaxDynamicSharedMemorySize, QKV_SMEM);
    cudaFuncSetAttribute(attn_mma, cudaFuncAttributeMaxDynamicSharedMemorySize, SMEM_ATTN);
    cudaFuncSetAttribute(proj_mma, cudaFuncAttributeMaxDynamicSharedMemorySize, PROJ_SMEM);

    prep_wqkv<<<768, 256>>>(w_qkv);
    prep_wp  <<<256, 256>>>(w_proj);
    ln_kernel<<<2048, 256>>>(x, ln_w, ln_b);
    qkv_mma  <<<dim3(48, 128), 256, QKV_SMEM>>>(scale);
    attn_mma <<<dim3(8, 128), 256, SMEM_ATTN>>>();
    proj_mma <<<128, 256, PROJ_SMEM>>>(b_proj, out);
}

// round 15
// speedup vs baseline: 5.9825x; 1.2788x over previous
#include <cuda_runtime.h>
#include <cuda_bf16.h>
#include <cuda_fp16.h>
#include <cstdint>

#define BATCH  16
#define NPAT   1024
#define EMB    128
#define HEADS  8
#define ROWS_TOT (BATCH*NPAT)      /* 16384 */
#define INNERD   (EMB*HEADS)       /* 1024  */
#define FLTMAX 3.402823466e38f

// ---------------- scratch (static device allocations; allowed) ----------------
// All tile stores are PRE-SWIZZLED in the exact smem layout the consumers use.
__device__ uint4 g_xnh[4194304/16],  g_xnl[4194304/16];    // xn  bf16 hi/lo
__device__ uint4 g_qh [33554432/16], g_ql [33554432/16];   // Q   fp16 hi/lo [128 bh][8 qt][128][128]
__device__ uint4 g_kh [33554432/16];                       // K   fp16 single [128 bh][16 jt][64][128]
__device__ uint4 g_vth[33554432/16], g_vtl[33554432/16];   // Vt  fp16 hi/lo [128 bh][16 jt][128d][64s]
__device__ uint4 g_aoh[33554432/16], g_aol[33554432/16];   // O   bf16 hi/lo [128 rt][128r][1024k]
__device__ uint4 g_wqh[786432/16],   g_wql[786432/16];     // wqkv^T bf16 [3072 n][128 k]
__device__ uint4 g_wph[262144/16],   g_wpl[262144/16];     // wproj^T bf16 [128 d][1024 k]

// ====================== PTX helpers ======================
__device__ __forceinline__ uint32_t smem_u32(const void* p) {
    uint32_t a;
    asm("{ .reg .u64 t; cvta.to.shared.u64 t, %1; cvt.u32.u64 %0, t; }" : "=r"(a) : "l"(p));
    return a;
}
__device__ __forceinline__ void ldsm4(uint32_t* r, uint32_t a) {
    asm volatile("ldmatrix.sync.aligned.m8n8.x4.shared.b16 {%0,%1,%2,%3}, [%4];"
        : "=r"(r[0]), "=r"(r[1]), "=r"(r[2]), "=r"(r[3]) : "r"(a));
}
// bf16 mma
__device__ __forceinline__ void mma16816(float* d, const uint32_t* a, const uint32_t* b) {
    asm volatile("mma.sync.aligned.m16n8k16.row.col.f32.bf16.bf16.f32 "
        "{%0,%1,%2,%3}, {%4,%5,%6,%7}, {%8,%9}, {%0,%1,%2,%3};"
        : "+f"(d[0]), "+f"(d[1]), "+f"(d[2]), "+f"(d[3])
        : "r"(a[0]), "r"(a[1]), "r"(a[2]), "r"(a[3]), "r"(b[0]), "r"(b[1]));
}
// fp16 mma
__device__ __forceinline__ void mma16816h(float* d, const uint32_t* a, const uint32_t* b) {
    asm volatile("mma.sync.aligned.m16n8k16.row.col.f32.f16.f16.f32 "
        "{%0,%1,%2,%3}, {%4,%5,%6,%7}, {%8,%9}, {%0,%1,%2,%3};"
        : "+f"(d[0]), "+f"(d[1]), "+f"(d[2]), "+f"(d[3])
        : "r"(a[0]), "r"(a[1]), "r"(a[2]), "r"(a[3]), "r"(b[0]), "r"(b[1]));
}
__device__ __forceinline__ void cpa16(uint32_t dst, const void* src) {
    asm volatile("cp.async.cg.shared.global [%0], [%1], 16;" :: "r"(dst), "l"(src));
}
#define CPA_COMMIT() asm volatile("cp.async.commit_group;" ::: "memory")
#define CPA_WAIT(n)  asm volatile("cp.async.wait_group %0;" :: "n"(n) : "memory")

// bf16 split helpers (qkv/proj path)
__device__ __forceinline__ uint32_t bfpack(__nv_bfloat16 a, __nv_bfloat16 b) {
    __nv_bfloat162 t = __halves2bfloat162(a, b);
    return *reinterpret_cast<uint32_t*>(&t);
}
__device__ __forceinline__ void bsplit(float x, __nv_bfloat16& h, __nv_bfloat16& l) {
    h = __float2bfloat16(x);
    l = __float2bfloat16(x - __bfloat162float(h));
}
__device__ __forceinline__ void bsplit2(float a, float b, uint32_t& hi, uint32_t& lo) {
    __nv_bfloat16 ha, la, hb, lb;
    bsplit(a, ha, la); bsplit(b, hb, lb);
    hi = bfpack(ha, hb); lo = bfpack(la, lb);
}
// fp16 helpers (attention path)
__device__ __forceinline__ uint32_t hpack(__half a, __half b) {
    __half2 t = __halves2half2(a, b);
    return *reinterpret_cast<uint32_t*>(&t);
}
__device__ __forceinline__ uint32_t hpack2(float a, float b) {
    return hpack(__float2half_rn(a), __float2half_rn(b));
}
__device__ __forceinline__ void hsplit2(float a, float b, uint32_t& hi, uint32_t& lo) {
    __half ha = __float2half_rn(a), hb = __float2half_rn(b);
    __half la = __float2half_rn(a - __half2float(ha));
    __half lb = __float2half_rn(b - __half2float(hb));
    hi = hpack(ha, hb); lo = hpack(la, lb);
}

// =============================== prep kernels ===============================
__global__ void prep_wqkv(const float* __restrict__ wq) {
    int idx = blockIdx.x*256 + threadIdx.x;          // 196608
    int n = idx >> 6, kp = (idx & 63) << 1;
    float a = wq[kp*3072 + n], b = wq[(kp+1)*3072 + n];
    uint32_t hi, lo; bsplit2(a, b, hi, lo);
    uint32_t off = (uint32_t)(n*256 + (((kp>>3) ^ (n&7))<<4) + (kp&7)*2);
    *(uint32_t*)((char*)g_wqh + off) = hi;
    *(uint32_t*)((char*)g_wql + off) = lo;
}
__global__ void prep_wp(const float* __restrict__ wp) {
    int idx = blockIdx.x*256 + threadIdx.x;          // 65536
    int d = idx >> 9, kp = (idx & 511) << 1;
    float a = wp[kp*128 + d], b = wp[(kp+1)*128 + d];
    uint32_t hi, lo; bsplit2(a, b, hi, lo);
    uint32_t off = (uint32_t)(d*2048 + (((kp>>3) ^ (d&7))<<4) + (kp&7)*2);
    *(uint32_t*)((char*)g_wph + off) = hi;
    *(uint32_t*)((char*)g_wpl + off) = lo;
}

// =============================== LayerNorm (warp-per-row) ===============================
__global__ void __launch_bounds__(256) ln_kernel(const float* __restrict__ x,
                                                 const float* __restrict__ w,
                                                 const float* __restrict__ b) {
    int wid = threadIdx.x >> 5, lane = threadIdx.x & 31;
    int row = blockIdx.x*8 + wid;
    float4 v = *(const float4*)&x[row*EMB + lane*4];
    float s = v.x + v.y + v.z + v.w;
    #pragma unroll
    for (int o = 16; o; o >>= 1) s += __shfl_xor_sync(0xffffffffu, s, o);
    float mean = s * (1.0f/EMB);
    float d0 = v.x - mean, d1 = v.y - mean, d2 = v.z - mean, d3 = v.w - mean;
    float q = d0*d0 + d1*d1 + d2*d2 + d3*d3;
    #pragma unroll
    for (int o = 16; o; o >>= 1) q += __shfl_xor_sync(0xffffffffu, q, o);
    float rinv = rsqrtf(q * (1.0f/EMB) + 1e-5f);
    float4 wv = *(const float4*)&w[lane*4];
    float4 bv = *(const float4*)&b[lane*4];
    float xn0 = d0*rinv*wv.x + bv.x, xn1 = d1*rinv*wv.y + bv.y;
    float xn2 = d2*rinv*wv.z + bv.z, xn3 = d3*rinv*wv.w + bv.w;
    uint32_t h0, l0, h1, l1;
    bsplit2(xn0, xn1, h0, l0);
    bsplit2(xn2, xn3, h1, l1);
    int rt = row >> 7, rl = row & 127, dd = lane*4;
    uint32_t off = (uint32_t)(rt*32768 + rl*256 + (((dd>>3) ^ (rl&7))<<4) + (dd&7)*2);
    *(uint2*)((char*)g_xnh + off) = make_uint2(h0, h1);
    *(uint2*)((char*)g_xnl + off) = make_uint2(l0, l1);
}

// =============================== QKV GEMM (mma.sync bf16 3-term) ===============================
// Epilogue emits fp16 tiles for attention: Q hi/lo (scale folded), K single, Vt hi/lo.
#define QKV_SMEM 98304
__global__ void __launch_bounds__(256, 2) qkv_mma(const float* __restrict__ scale) {
    extern __shared__ char smc[];
    uint32_t sb = smem_u32(smc);
    int tid = threadIdx.x, w = tid >> 5, L = tid & 31;
    int rowbase = blockIdx.y * 128;
    int colbase = blockIdx.x * 64;

    {
        const char* axh = (const char*)g_xnh + (size_t)blockIdx.y*32768;
        const char* axl = (const char*)g_xnl + (size_t)blockIdx.y*32768;
        const char* bxh = (const char*)g_wqh + (size_t)colbase*256;
        const char* bxl = (const char*)g_wql + (size_t)colbase*256;
        #pragma unroll
        for (int it = 0; it < 8; it++) {
            uint32_t o = (uint32_t)(it*256 + tid)*16;
            cpa16(sb + o,         axh + o);
            cpa16(sb + 32768 + o, axl + o);
        }
        #pragma unroll
        for (int it = 0; it < 4; it++) {
            uint32_t o = (uint32_t)(it*256 + tid)*16;
            cpa16(sb + 65536 + o, bxh + o);
            cpa16(sb + 81920 + o, bxl + o);
        }
        CPA_COMMIT(); CPA_WAIT(0);
    }
    __syncthreads();

    int l7 = L & 7;
    int rowA = (w << 4) + ((L >> 3) & 1)*8 + l7;
    int cA = L >> 4;
    uint32_t aBH = sb + rowA*256, aBL = sb + 32768 + rowA*256;
    int rB = (L & 7) + ((L >> 4) & 1)*8;
    int csel = (L >> 3) & 1;

    float acc[8][4] = {};
    #pragma unroll
    for (int kc = 0; kc < 8; kc++) {
        uint32_t ah[4], al[4];
        uint32_t ap = (uint32_t)(((kc*2 + cA) ^ l7) << 4);
        ldsm4(ah, aBH + ap);  ldsm4(al, aBL + ap);
        uint32_t cp = (uint32_t)(((kc*2 + csel) ^ l7) << 4);
        #pragma unroll
        for (int nbp = 0; nbp < 4; nbp++) {
            uint32_t bh4[4], bl4[4];
            uint32_t bo = (uint32_t)((nbp*16 + rB)*256) + cp;
            ldsm4(bh4, sb + 65536 + bo);
            ldsm4(bl4, sb + 81920 + bo);
            mma16816(acc[2*nbp],   ah, bh4);     mma16816(acc[2*nbp],   ah, bl4);
            mma16816(acc[2*nbp],   al, bh4);
            mma16816(acc[2*nbp+1], ah, bh4+2);   mma16816(acc[2*nbp+1], ah, bl4+2);
            mma16816(acc[2*nbp+1], al, bh4+2);
        }
    }

    int g = L >> 2, t2 = (L & 3)*2;
    int r0 = (w << 4) + g, r1 = r0 + 8;
    int section = colbase >> 10, h = (colbase & 1023) >> 7, dbase = colbase & 127;
    int b = rowbase >> 10, n0 = rowbase & 1023;
    int bh = b*HEADS + h;

    if (section == 0) {
        float sc = scale[h];
        char* dh = (char*)g_qh + (size_t)(bh*8 + (n0 >> 7))*32768;
        char* dl = (char*)g_ql + (size_t)(bh*8 + (n0 >> 7))*32768;
        #pragma unroll
        for (int nb = 0; nb < 8; nb++) {
            int c16 = (dbase + nb*8 + t2) >> 3;
            uint32_t hi, lo;
            uint32_t o0 = (uint32_t)(r0*256 + ((c16 ^ (r0&7))<<4) + t2*2);
            hsplit2(acc[nb][0]*sc, acc[nb][1]*sc, hi, lo);
            *(uint32_t*)(dh + o0) = hi;  *(uint32_t*)(dl + o0) = lo;
            uint32_t o1 = (uint32_t)(r1*256 + ((c16 ^ (r1&7))<<4) + t2*2);
            hsplit2(acc[nb][2]*sc, acc[nb][3]*sc, hi, lo);
            *(uint32_t*)(dh + o1) = hi;  *(uint32_t*)(dl + o1) = lo;
        }
    } else if (section == 1) {
        // K single fp16
        char* dh = (char*)g_kh + (size_t)(bh*16 + (n0 >> 6))*16384;
        int t0 = (r0 >> 6)*16384, rl0 = r0 & 63;
        int t1 = (r1 >> 6)*16384, rl1 = r1 & 63;
        #pragma unroll
        for (int nb = 0; nb < 8; nb++) {
            int c16 = (dbase + nb*8 + t2) >> 3;
            uint32_t o0 = (uint32_t)(t0 + rl0*256 + ((c16 ^ (rl0&7))<<4) + t2*2);
            *(uint32_t*)(dh + o0) = hpack2(acc[nb][0], acc[nb][1]);
            uint32_t o1 = (uint32_t)(t1 + rl1*256 + ((c16 ^ (rl1&7))<<4) + t2*2);
            *(uint32_t*)(dh + o1) = hpack2(acc[nb][2], acc[nb][3]);
        }
    } else {
        __syncthreads();
        float* stg = (float*)smc;                       // [128 s][68]
        #pragma unroll
        for (int nb = 0; nb < 8; nb++) {
            int dl0 = nb*8 + t2;
            stg[r0*68 + dl0] = acc[nb][0];  stg[r0*68 + dl0 + 1] = acc[nb][1];
            stg[r1*68 + dl0] = acc[nb][2];  stg[r1*68 + dl0 + 1] = acc[nb][3];
        }
        __syncthreads();
        char* vh = (char*)g_vth + (size_t)(bh*16 + (n0 >> 6))*16384;
        char* vl = (char*)g_vtl + (size_t)(bh*16 + (n0 >> 6))*16384;
        #pragma unroll
        for (int it = 0; it < 4; it++) {
            int e = it*256 + tid, dloc = e & 63, c8 = e >> 6;
            uint32_t hi4[4], lo4[4];
            #pragma unroll
            for (int p = 0; p < 4; p++)
                hsplit2(stg[(c8*8 + 2*p)*68 + dloc], stg[(c8*8 + 2*p + 1)*68 + dloc],
                        hi4[p], lo4[p]);
            int d = dbase + dloc;
            uint32_t off = (uint32_t)((c8 >> 3)*16384 + d*128 + (((c8 & 7) ^ (d&7))<<4));
            *(uint4*)(vh + off) = make_uint4(hi4[0], hi4[1], hi4[2], hi4[3]);
            *(uint4*)(vl + off) = make_uint4(lo4[0], lo4[1], lo4[2], lo4[3]);
        }
    }
}

// ====================== fp16 2-MMA flash attention ======================
// grid (8 qt, 128 bh), 256 thr. Q(hi/lo fp16) resident; K single fp16; V hi/lo fp16.
// S = Qh·K + Ql·K ; O = P·Vh + P·Vl  (P single fp16).
#define AQ_H 0
#define AQ_L 32768
#define ABUF(b) (65536 + (b)*49152)     /* KH 16KB, VH 16KB, VL 16KB */
#define SMEM_ATTN 163840
__global__ void __launch_bounds__(256, 1) attn_mma() {
    extern __shared__ char smc[];
    uint32_t sb = smem_u32(smc);
    int tid = threadIdx.x, w = tid >> 5, L = tid & 31;
    int qt = blockIdx.x, bh = blockIdx.y;
    int qbase = qt * 128;

    {
        const char* qh = (const char*)g_qh + (size_t)(bh*8 + qt)*32768;
        const char* ql = (const char*)g_ql + (size_t)(bh*8 + qt)*32768;
        #pragma unroll
        for (int it = 0; it < 8; it++) {
            uint32_t o = (uint32_t)(it*256 + tid)*16;
            cpa16(sb + AQ_H + o, qh + o);
            cpa16(sb + AQ_L + o, ql + o);
        }
        const char* kh = (const char*)g_kh + (size_t)(bh*16)*16384;
        const char* vh = (const char*)g_vth + (size_t)(bh*16)*16384;
        const char* vl = (const char*)g_vtl + (size_t)(bh*16)*16384;
        uint32_t dst = sb + ABUF(0);
        #pragma unroll
        for (int it = 0; it < 4; it++) {
            uint32_t o = (uint32_t)(it*256 + tid)*16;
            cpa16(dst + o,         kh + o);
            cpa16(dst + 16384 + o, vh + o);
            cpa16(dst + 32768 + o, vl + o);
        }
        CPA_COMMIT();
    }

    int l7 = L & 7;
    int rowA = (w << 4) + ((L >> 3) & 1)*8 + l7;
    int cA = L >> 4;
    uint32_t aBH = sb + AQ_H + rowA*256, aBL = sb + AQ_L + rowA*256;
    int rB = (L & 7) + ((L >> 4) & 1)*8;
    int csel = (L >> 3) & 1;
    int g = L >> 2, t2 = (L & 3)*2;
    int rg0 = qbase + (w << 4) + g, rg1 = rg0 + 8;

    float m0 = -FLTMAX, m1 = -FLTMAX, ls0 = 0.f, ls1 = 0.f;
    float O[16][4];
    #pragma unroll
    for (int nb = 0; nb < 16; nb++) { O[nb][0]=0.f; O[nb][1]=0.f; O[nb][2]=0.f; O[nb][3]=0.f; }

    #pragma unroll 1
    for (int j = 0; j < 16; j++) {
        if (j < 15) {
            int jn = j + 1;
            const char* kh = (const char*)g_kh + (size_t)(bh*16 + jn)*16384;
            const char* vh = (const char*)g_vth + (size_t)(bh*16 + jn)*16384;
            const char* vl = (const char*)g_vtl + (size_t)(bh*16 + jn)*16384;
            uint32_t dst = sb + ABUF(jn & 1);
            #pragma unroll
            for (int it = 0; it < 4; it++) {
                uint32_t o = (uint32_t)(it*256 + tid)*16;
                cpa16(dst + o,         kh + o);
                cpa16(dst + 16384 + o, vh + o);
                cpa16(dst + 32768 + o, vl + o);
            }
            CPA_COMMIT(); CPA_WAIT(1);
        } else {
            CPA_WAIT(0);
        }
        __syncthreads();
        uint32_t kbH = sb + ABUF(j & 1);
        uint32_t vbH = kbH + 16384, vbL = kbH + 32768;

        // ---- S = Qh K + Ql K : m16 x n64 per warp, k=128 ----
        float S[8][4];
        #pragma unroll
        for (int nb = 0; nb < 8; nb++) { S[nb][0]=0.f; S[nb][1]=0.f; S[nb][2]=0.f; S[nb][3]=0.f; }
        #pragma unroll
        for (int kc = 0; kc < 8; kc++) {
            uint32_t ah[4], al[4];
            uint32_t ap = (uint32_t)(((kc*2 + cA) ^ l7) << 4);
            ldsm4(ah, aBH + ap);  ldsm4(al, aBL + ap);
            uint32_t cp = (uint32_t)(((kc*2 + csel) ^ l7) << 4);
            #pragma unroll
            for (int nbp = 0; nbp < 4; nbp++) {
                uint32_t bk[4];
                uint32_t bo = (uint32_t)((nbp*16 + rB)*256) + cp;
                ldsm4(bk, kbH + bo);
                mma16816h(S[2*nbp],   ah, bk);    mma16816h(S[2*nbp],   al, bk);
                mma16816h(S[2*nbp+1], ah, bk+2);  mma16816h(S[2*nbp+1], al, bk+2);
            }
        }

        if ((j >> 1) == qt) {
            int colbase = j*64;
            #pragma unroll
            for (int nb = 0; nb < 8; nb++) {
                int c0 = colbase + nb*8 + t2;
                if (c0     == rg0) S[nb][0] = -FLTMAX;
                if (c0 + 1 == rg0) S[nb][1] = -FLTMAX;
                if (c0     == rg1) S[nb][2] = -FLTMAX;
                if (c0 + 1 == rg1) S[nb][3] = -FLTMAX;
            }
        }

        // ---- online softmax ----
        float rmax0 = -FLTMAX, rmax1 = -FLTMAX;
        #pragma unroll
        for (int nb = 0; nb < 8; nb++) {
            rmax0 = fmaxf(rmax0, fmaxf(S[nb][0], S[nb][1]));
            rmax1 = fmaxf(rmax1, fmaxf(S[nb][2], S[nb][3]));
        }
        rmax0 = fmaxf(rmax0, __shfl_xor_sync(0xffffffffu, rmax0, 1));
        rmax0 = fmaxf(rmax0, __shfl_xor_sync(0xffffffffu, rmax0, 2));
        rmax1 = fmaxf(rmax1, __shfl_xor_sync(0xffffffffu, rmax1, 1));
        rmax1 = fmaxf(rmax1, __shfl_xor_sync(0xffffffffu, rmax1, 2));
        float mn0 = fmaxf(m0, rmax0), mn1 = fmaxf(m1, rmax1);
        float cr0 = __expf(m0 - mn0), cr1 = __expf(m1 - mn1);
        m0 = mn0; m1 = mn1;
        float rs0 = 0.f, rs1 = 0.f;
        #pragma unroll
        for (int nb = 0; nb < 8; nb++) {
            S[nb][0] = __expf(S[nb][0] - mn0); rs0 += S[nb][0];
            S[nb][1] = __expf(S[nb][1] - mn0); rs0 += S[nb][1];
            S[nb][2] = __expf(S[nb][2] - mn1); rs1 += S[nb][2];
            S[nb][3] = __expf(S[nb][3] - mn1); rs1 += S[nb][3];
        }
        rs0 += __shfl_xor_sync(0xffffffffu, rs0, 1);
        rs0 += __shfl_xor_sync(0xffffffffu, rs0, 2);
        rs1 += __shfl_xor_sync(0xffffffffu, rs1, 1);
        rs1 += __shfl_xor_sync(0xffffffffu, rs1, 2);
        ls0 = ls0*cr0 + rs0;
        ls1 = ls1*cr1 + rs1;
        #pragma unroll
        for (int nb = 0; nb < 16; nb++) {
            O[nb][0] *= cr0;  O[nb][1] *= cr0;
            O[nb][2] *= cr1;  O[nb][3] *= cr1;
        }

        // ---- O += P V : P single fp16 A-frag; V hi/lo from smem ----
        #pragma unroll
        for (int kc = 0; kc < 4; kc++) {
            uint32_t ah[4];
            ah[0] = hpack2(S[2*kc][0],   S[2*kc][1]);
            ah[1] = hpack2(S[2*kc][2],   S[2*kc][3]);
            ah[2] = hpack2(S[2*kc+1][0], S[2*kc+1][1]);
            ah[3] = hpack2(S[2*kc+1][2], S[2*kc+1][3]);
            uint32_t cp = (uint32_t)(((kc*2 + csel) ^ l7) << 4);
            #pragma unroll
            for (int nbp = 0; nbp < 8; nbp++) {
                uint32_t vh4[4], vl4[4];
                uint32_t bo = (uint32_t)((nbp*16 + rB)*128) + cp;
                ldsm4(vh4, vbH + bo);  ldsm4(vl4, vbL + bo);
                mma16816h(O[2*nbp],   ah, vh4);    mma16816h(O[2*nbp],   ah, vl4);
                mma16816h(O[2*nbp+1], ah, vh4+2);  mma16816h(O[2*nbp+1], ah, vl4+2);
            }
        }
        __syncthreads();
    }

    // ---- epilogue: normalize, split bf16, write pre-swizzled O tiles for proj ----
    float inv0 = 1.0f / ls0, inv1 = 1.0f / ls1;
    int bb = bh >> 3, h = bh & 7;
    int rowtile = bb*8 + qt;
    int rl0 = (w << 4) + g, rl1 = rl0 + 8;
    char* aoh = (char*)g_aoh + (size_t)rowtile*262144;
    char* aol = (char*)g_aol + (size_t)rowtile*262144;
    #pragma unroll
    for (int nb = 0; nb < 16; nb++) {
        int c16 = h*16 + nb;
        uint32_t hi, lo;
        uint32_t o0 = (uint32_t)(rl0*2048 + ((c16 ^ (rl0&7))<<4) + t2*2);
        bsplit2(O[nb][0]*inv0, O[nb][1]*inv0, hi, lo);
        *(uint32_t*)(aoh + o0) = hi;  *(uint32_t*)(aol + o0) = lo;
        uint32_t o1 = (uint32_t)(rl1*2048 + ((c16 ^ (rl1&7))<<4) + t2*2);
        bsplit2(O[nb][2]*inv1, O[nb][3]*inv1, hi, lo);
        *(uint32_t*)(aoh + o1) = hi;  *(uint32_t*)(aol + o1) = lo;
    }
}

// =============================== Output projection (bf16 3-term, double-buffered) ===============================
#define PROJ_SMEM 131072
__global__ void __launch_bounds__(256, 1) proj_mma(const float* __restrict__ bias,
                                                   float* __restrict__ out) {
    extern __shared__ char smc[];
    uint32_t sb = smem_u32(smc);
    int tid = threadIdx.x, w = tid >> 5, L = tid & 31;
    int rowtile = blockIdx.x;
    const char* aoh = (const char*)g_aoh + (size_t)rowtile*262144;
    const char* aol = (const char*)g_aol + (size_t)rowtile*262144;

    int l7 = L & 7;
    int rowA = (w << 4) + ((L >> 3) & 1)*8 + l7;
    int cA = L >> 4;
    int rB = (L & 7) + ((L >> 4) & 1)*8;
    int csel = (L >> 3) & 1;
    int g = L >> 2, t2 = (L & 3)*2;

    auto prefetch = [&](int kb, int st) {
        uint32_t base = sb + st*65536;
        #pragma unroll
        for (int it = 0; it < 4; it++) {
            int e = it*256 + tid, r = e >> 3, jj = e & 7;
            uint32_t go = (uint32_t)(r*2048 + kb*128 + ((jj ^ (r&7))<<4));
            uint32_t so = (uint32_t)(r*128 + ((jj ^ (r&7))<<4));
            cpa16(base + so,          aoh + go);
            cpa16(base + 16384 + so,  aol + go);
            cpa16(base + 32768 + so,  (const char*)g_wph + go);
            cpa16(base + 49152 + so,  (const char*)g_wpl + go);
        }
        CPA_COMMIT();
    };

    float acc[16][4];
    #pragma unroll
    for (int nb = 0; nb < 16; nb++) { acc[nb][0]=0.f; acc[nb][1]=0.f; acc[nb][2]=0.f; acc[nb][3]=0.f; }

    prefetch(0, 0);
    #pragma unroll 1
    for (int kb = 0; kb < 16; kb++) {
        if (kb < 15) { prefetch(kb + 1, (kb + 1) & 1); CPA_WAIT(1); }
        else          CPA_WAIT(0);
        __syncthreads();
        uint32_t base = sb + (kb & 1)*65536;
        uint32_t aH = base + rowA*128, aL = base + 16384 + rowA*128;
        #pragma unroll
        for (int kc = 0; kc < 4; kc++) {
            uint32_t ah[4], al[4];
            uint32_t ap = (uint32_t)(((kc*2 + cA) ^ l7) << 4);
            ldsm4(ah, aH + ap);  ldsm4(al, aL + ap);
            uint32_t cp = (uint32_t)(((kc*2 + csel) ^ l7) << 4);
            #pragma unroll
            for (int nbp = 0; nbp < 8; nbp++) {
                uint32_t bh4[4], bl4[4];
                uint32_t bo = (uint32_t)((nbp*16 + rB)*128) + cp;
                ldsm4(bh4, base + 32768 + bo);  ldsm4(bl4, base + 49152 + bo);
                mma16816(acc[2*nbp],   ah, bh4);    mma16816(acc[2*nbp],   ah, bl4);
                mma16816(acc[2*nbp],   al, bh4);
                mma16816(acc[2*nbp+1], ah, bh4+2);  mma16816(acc[2*nbp+1], ah, bl4+2);
                mma16816(acc[2*nbp+1], al, bh4+2);
            }
        }
        __syncthreads();
    }

    int r0 = rowtile*128 + (w << 4) + g, r1 = r0 + 8;
    #pragma unroll
    for (int nb = 0; nb < 16; nb++) {
        int col = nb*8 + t2;
        float b0 = bias[col], b1 = bias[col + 1];
        *(float2*)&out[r0*128 + col] = make_float2(acc[nb][0] + b0, acc[nb][1] + b1);
        *(float2*)&out[r1*128 + col] = make_float2(acc[nb][2] + b0, acc[nb][3] + b1);
    }
}

// =============================== launch ===============================
extern "C" void kernel_launch(void* const* d_in, const int* in_sizes, int n_in,
                              void* d_out, int out_size) {
    const float* x      = (const float*)d_in[0];
    const float* ln_w   = (const float*)d_in[1];
    const float* ln_b   = (const float*)d_in[2];
    const float* w_qkv  = (const float*)d_in[3];
    const float* scale  = (const float*)d_in[4];
    const float* w_proj = (const float*)d_in[5];
    const float* b_proj = (const float*)d_in[6];
    float* out = (float*)d_out;

    cudaFuncSetAttribute(qkv_mma,  cudaFuncAttributeMaxDynamicSharedMemorySize, QKV_SMEM);
    cudaFuncSetAttribute(attn_mma, cudaFuncAttributeMaxDynamicSharedMemorySize, SMEM_ATTN);
    cudaFuncSetAttribute(proj_mma, cudaFuncAttributeMaxDynamicSharedMemorySize, PROJ_SMEM);

    prep_wqkv<<<768, 256>>>(w_qkv);
    prep_wp  <<<256, 256>>>(w_proj);
    ln_kernel<<<2048, 256>>>(x, ln_w, ln_b);
    qkv_mma  <<<dim3(48, 128), 256, QKV_SMEM>>>(scale);
    attn_mma <<<dim3(8, 128), 256, SMEM_ATTN>>>();
    proj_mma <<<128, 256, PROJ_SMEM>>>(b_proj, out);
}

// round 16
// speedup vs baseline: 8.8888x; 1.4858x over previous
#include <cuda_runtime.h>
#include <cuda_bf16.h>
#include <cuda_fp16.h>
#include <cstdint>

#define BATCH  16
#define NPAT   1024
#define EMB    128
#define HEADS  8
#define ROWS_TOT (BATCH*NPAT)      /* 16384 */
#define INNERD   (EMB*HEADS)       /* 1024  */
#define FLTMAX 3.402823466e38f

// ---------------- scratch (static device allocations; allowed) ----------------
// All tiles PRE-SWIZZLED in the exact smem layout the consumers use. fp16 throughout.
__device__ uint4 g_xn [4194304/16];                        // xn  fp16 single [128 rt][128r][128k]
__device__ uint4 g_q  [33554432/16];                       // Q   fp16 single [128 bh][8 qt][128][128]
__device__ uint4 g_kh [33554432/16];                       // K   fp16 single [128 bh][16 jt][64][128]
__device__ uint4 g_vth[33554432/16];                       // Vt  fp16 single [128 bh][16 jt][128d][64s]
__device__ uint4 g_ao [33554432/16];                       // O   fp16 single [128 rt][128r][1024k]
__device__ uint4 g_wqh[786432/16],   g_wql[786432/16];     // wqkv^T fp16 hi/lo [3072 n][128 k]
__device__ uint4 g_wph[262144/16],   g_wpl[262144/16];     // wproj^T fp16 hi/lo [128 d][1024 k]

// ====================== PTX helpers ======================
__device__ __forceinline__ uint32_t smem_u32(const void* p) {
    uint32_t a;
    asm("{ .reg .u64 t; cvta.to.shared.u64 t, %1; cvt.u32.u64 %0, t; }" : "=r"(a) : "l"(p));
    return a;
}
__device__ __forceinline__ void ldsm4(uint32_t* r, uint32_t a) {
    asm volatile("ldmatrix.sync.aligned.m8n8.x4.shared.b16 {%0,%1,%2,%3}, [%4];"
        : "=r"(r[0]), "=r"(r[1]), "=r"(r[2]), "=r"(r[3]) : "r"(a));
}
__device__ __forceinline__ void mma16816h(float* d, const uint32_t* a, const uint32_t* b) {
    asm volatile("mma.sync.aligned.m16n8k16.row.col.f32.f16.f16.f32 "
        "{%0,%1,%2,%3}, {%4,%5,%6,%7}, {%8,%9}, {%0,%1,%2,%3};"
        : "+f"(d[0]), "+f"(d[1]), "+f"(d[2]), "+f"(d[3])
        : "r"(a[0]), "r"(a[1]), "r"(a[2]), "r"(a[3]), "r"(b[0]), "r"(b[1]));
}
__device__ __forceinline__ void cpa16(uint32_t dst, const void* src) {
    asm volatile("cp.async.cg.shared.global [%0], [%1], 16;" :: "r"(dst), "l"(src));
}
#define CPA_COMMIT() asm volatile("cp.async.commit_group;" ::: "memory")
#define CPA_WAIT(n)  asm volatile("cp.async.wait_group %0;" :: "n"(n) : "memory")

__device__ __forceinline__ uint32_t hpack(__half a, __half b) {
    __half2 t = __halves2half2(a, b);
    return *reinterpret_cast<uint32_t*>(&t);
}
__device__ __forceinline__ uint32_t hpack2(float a, float b) {
    return hpack(__float2half_rn(a), __float2half_rn(b));
}
__device__ __forceinline__ void hsplit2(float a, float b, uint32_t& hi, uint32_t& lo) {
    __half ha = __float2half_rn(a), hb = __float2half_rn(b);
    __half la = __float2half_rn(a - __half2float(ha));
    __half lb = __float2half_rn(b - __half2float(hb));
    hi = hpack(ha, hb); lo = hpack(la, lb);
}

// =============================== prep kernels ===============================
__global__ void prep_wqkv(const float* __restrict__ wq) {
    int idx = blockIdx.x*256 + threadIdx.x;          // 196608
    int n = idx >> 6, kp = (idx & 63) << 1;
    float a = wq[kp*3072 + n], b = wq[(kp+1)*3072 + n];
    uint32_t hi, lo; hsplit2(a, b, hi, lo);
    uint32_t off = (uint32_t)(n*256 + (((kp>>3) ^ (n&7))<<4) + (kp&7)*2);
    *(uint32_t*)((char*)g_wqh + off) = hi;
    *(uint32_t*)((char*)g_wql + off) = lo;
}
__global__ void prep_wp(const float* __restrict__ wp) {
    int idx = blockIdx.x*256 + threadIdx.x;          // 65536
    int d = idx >> 9, kp = (idx & 511) << 1;
    float a = wp[kp*128 + d], b = wp[(kp+1)*128 + d];
    uint32_t hi, lo; hsplit2(a, b, hi, lo);
    uint32_t off = (uint32_t)(d*2048 + (((kp>>3) ^ (d&7))<<4) + (kp&7)*2);
    *(uint32_t*)((char*)g_wph + off) = hi;
    *(uint32_t*)((char*)g_wpl + off) = lo;
}

// =============================== LayerNorm (warp-per-row, fp16 out) ===============================
__global__ void __launch_bounds__(256) ln_kernel(const float* __restrict__ x,
                                                 const float* __restrict__ w,
                                                 const float* __restrict__ b) {
    int wid = threadIdx.x >> 5, lane = threadIdx.x & 31;
    int row = blockIdx.x*8 + wid;
    float4 v = *(const float4*)&x[row*EMB + lane*4];
    float s = v.x + v.y + v.z + v.w;
    #pragma unroll
    for (int o = 16; o; o >>= 1) s += __shfl_xor_sync(0xffffffffu, s, o);
    float mean = s * (1.0f/EMB);
    float d0 = v.x - mean, d1 = v.y - mean, d2 = v.z - mean, d3 = v.w - mean;
    float q = d0*d0 + d1*d1 + d2*d2 + d3*d3;
    #pragma unroll
    for (int o = 16; o; o >>= 1) q += __shfl_xor_sync(0xffffffffu, q, o);
    float rinv = rsqrtf(q * (1.0f/EMB) + 1e-5f);
    float4 wv = *(const float4*)&w[lane*4];
    float4 bv = *(const float4*)&b[lane*4];
    float xn0 = d0*rinv*wv.x + bv.x, xn1 = d1*rinv*wv.y + bv.y;
    float xn2 = d2*rinv*wv.z + bv.z, xn3 = d3*rinv*wv.w + bv.w;
    int rt = row >> 7, rl = row & 127, dd = lane*4;
    uint32_t off = (uint32_t)(rt*32768 + rl*256 + (((dd>>3) ^ (rl&7))<<4) + (dd&7)*2);
    *(uint2*)((char*)g_xn + off) = make_uint2(hpack2(xn0, xn1), hpack2(xn2, xn3));
}

// =============================== QKV GEMM (fp16 2-term: xn single, W hi/lo) ===============================
// smem: A 32KB @0, BH 16KB @32768, BL 16KB @49152
#define QKV_SMEM 65536
__global__ void __launch_bounds__(256, 2) qkv_mma(const float* __restrict__ scale) {
    extern __shared__ char smc[];
    uint32_t sb = smem_u32(smc);
    int tid = threadIdx.x, w = tid >> 5, L = tid & 31;
    int rowbase = blockIdx.y * 128;
    int colbase = blockIdx.x * 64;

    {
        const char* ax  = (const char*)g_xn  + (size_t)blockIdx.y*32768;
        const char* bxh = (const char*)g_wqh + (size_t)colbase*256;
        const char* bxl = (const char*)g_wql + (size_t)colbase*256;
        #pragma unroll
        for (int it = 0; it < 8; it++) {
            uint32_t o = (uint32_t)(it*256 + tid)*16;
            cpa16(sb + o, ax + o);
        }
        #pragma unroll
        for (int it = 0; it < 4; it++) {
            uint32_t o = (uint32_t)(it*256 + tid)*16;
            cpa16(sb + 32768 + o, bxh + o);
            cpa16(sb + 49152 + o, bxl + o);
        }
        CPA_COMMIT(); CPA_WAIT(0);
    }
    __syncthreads();

    int l7 = L & 7;
    int rowA = (w << 4) + ((L >> 3) & 1)*8 + l7;
    int cA = L >> 4;
    uint32_t aB = sb + rowA*256;
    int rB = (L & 7) + ((L >> 4) & 1)*8;
    int csel = (L >> 3) & 1;

    float acc[8][4] = {};
    #pragma unroll
    for (int kc = 0; kc < 8; kc++) {
        uint32_t a4[4];
        uint32_t ap = (uint32_t)(((kc*2 + cA) ^ l7) << 4);
        ldsm4(a4, aB + ap);
        uint32_t cp = (uint32_t)(((kc*2 + csel) ^ l7) << 4);
        #pragma unroll
        for (int nbp = 0; nbp < 4; nbp++) {
            uint32_t bh4[4], bl4[4];
            uint32_t bo = (uint32_t)((nbp*16 + rB)*256) + cp;
            ldsm4(bh4, sb + 32768 + bo);
            ldsm4(bl4, sb + 49152 + bo);
            mma16816h(acc[2*nbp],   a4, bh4);     mma16816h(acc[2*nbp],   a4, bl4);
            mma16816h(acc[2*nbp+1], a4, bh4+2);   mma16816h(acc[2*nbp+1], a4, bl4+2);
        }
    }

    int g = L >> 2, t2 = (L & 3)*2;
    int r0 = (w << 4) + g, r1 = r0 + 8;
    int section = colbase >> 10, h = (colbase & 1023) >> 7, dbase = colbase & 127;
    int b = rowbase >> 10, n0 = rowbase & 1023;
    int bh = b*HEADS + h;

    if (section == 0) {
        float sc = scale[h];
        char* dq = (char*)g_q + (size_t)(bh*8 + (n0 >> 7))*32768;
        #pragma unroll
        for (int nb = 0; nb < 8; nb++) {
            int c16 = (dbase + nb*8 + t2) >> 3;
            uint32_t o0 = (uint32_t)(r0*256 + ((c16 ^ (r0&7))<<4) + t2*2);
            *(uint32_t*)(dq + o0) = hpack2(acc[nb][0]*sc, acc[nb][1]*sc);
            uint32_t o1 = (uint32_t)(r1*256 + ((c16 ^ (r1&7))<<4) + t2*2);
            *(uint32_t*)(dq + o1) = hpack2(acc[nb][2]*sc, acc[nb][3]*sc);
        }
    } else if (section == 1) {
        char* dh = (char*)g_kh + (size_t)(bh*16 + (n0 >> 6))*16384;
        int t0 = (r0 >> 6)*16384, rl0 = r0 & 63;
        int t1 = (r1 >> 6)*16384, rl1 = r1 & 63;
        #pragma unroll
        for (int nb = 0; nb < 8; nb++) {
            int c16 = (dbase + nb*8 + t2) >> 3;
            uint32_t o0 = (uint32_t)(t0 + rl0*256 + ((c16 ^ (rl0&7))<<4) + t2*2);
            *(uint32_t*)(dh + o0) = hpack2(acc[nb][0], acc[nb][1]);
            uint32_t o1 = (uint32_t)(t1 + rl1*256 + ((c16 ^ (rl1&7))<<4) + t2*2);
            *(uint32_t*)(dh + o1) = hpack2(acc[nb][2], acc[nb][3]);
        }
    } else {
        __syncthreads();
        float* stg = (float*)smc;                       // [128 s][68] reuse smem
        #pragma unroll
        for (int nb = 0; nb < 8; nb++) {
            int dl0 = nb*8 + t2;
            stg[r0*68 + dl0] = acc[nb][0];  stg[r0*68 + dl0 + 1] = acc[nb][1];
            stg[r1*68 + dl0] = acc[nb][2];  stg[r1*68 + dl0 + 1] = acc[nb][3];
        }
        __syncthreads();
        char* vh = (char*)g_vth + (size_t)(bh*16 + (n0 >> 6))*16384;
        #pragma unroll
        for (int it = 0; it < 4; it++) {
            int e = it*256 + tid, dloc = e & 63, c8 = e >> 6;
            uint32_t hi4[4];
            #pragma unroll
            for (int p = 0; p < 4; p++)
                hi4[p] = hpack2(stg[(c8*8 + 2*p)*68 + dloc], stg[(c8*8 + 2*p + 1)*68 + dloc]);
            int d = dbase + dloc;
            uint32_t off = (uint32_t)((c8 >> 3)*16384 + d*128 + (((c8 & 7) ^ (d&7))<<4));
            *(uint4*)(vh + off) = make_uint4(hi4[0], hi4[1], hi4[2], hi4[3]);
        }
    }
}

// ====================== fp16 single-precision flash attention ======================
// grid (8 qt, 128 bh), 256 thr. S = Q·K (1 mma), O = P·V (1 mma). All single fp16.
#define AQ 0
#define ABUF(b) (32768 + (b)*32768)     /* K 16KB, V 16KB */
#define SMEM_ATTN 98304
__global__ void __launch_bounds__(256, 1) attn_mma() {
    extern __shared__ char smc[];
    uint32_t sb = smem_u32(smc);
    int tid = threadIdx.x, w = tid >> 5, L = tid & 31;
    int qt = blockIdx.x, bh = blockIdx.y;
    int qbase = qt * 128;

    {
        const char* qg = (const char*)g_q + (size_t)(bh*8 + qt)*32768;
        #pragma unroll
        for (int it = 0; it < 8; it++) {
            uint32_t o = (uint32_t)(it*256 + tid)*16;
            cpa16(sb + AQ + o, qg + o);
        }
        const char* kh = (const char*)g_kh + (size_t)(bh*16)*16384;
        const char* vh = (const char*)g_vth + (size_t)(bh*16)*16384;
        uint32_t dst = sb + ABUF(0);
        #pragma unroll
        for (int it = 0; it < 4; it++) {
            uint32_t o = (uint32_t)(it*256 + tid)*16;
            cpa16(dst + o,         kh + o);
            cpa16(dst + 16384 + o, vh + o);
        }
        CPA_COMMIT();
    }

    int l7 = L & 7;
    int rowA = (w << 4) + ((L >> 3) & 1)*8 + l7;
    int cA = L >> 4;
    uint32_t aB = sb + AQ + rowA*256;
    int rB = (L & 7) + ((L >> 4) & 1)*8;
    int csel = (L >> 3) & 1;
    int g = L >> 2, t2 = (L & 3)*2;
    int rg0 = qbase + (w << 4) + g, rg1 = rg0 + 8;

    float m0 = -FLTMAX, m1 = -FLTMAX, ls0 = 0.f, ls1 = 0.f;
    float O[16][4];
    #pragma unroll
    for (int nb = 0; nb < 16; nb++) { O[nb][0]=0.f; O[nb][1]=0.f; O[nb][2]=0.f; O[nb][3]=0.f; }

    #pragma unroll 1
    for (int j = 0; j < 16; j++) {
        if (j < 15) {
            int jn = j + 1;
            const char* kh = (const char*)g_kh + (size_t)(bh*16 + jn)*16384;
            const char* vh = (const char*)g_vth + (size_t)(bh*16 + jn)*16384;
            uint32_t dst = sb + ABUF(jn & 1);
            #pragma unroll
            for (int it = 0; it < 4; it++) {
                uint32_t o = (uint32_t)(it*256 + tid)*16;
                cpa16(dst + o,         kh + o);
                cpa16(dst + 16384 + o, vh + o);
            }
            CPA_COMMIT(); CPA_WAIT(1);
        } else {
            CPA_WAIT(0);
        }
        __syncthreads();
        uint32_t kb = sb + ABUF(j & 1);
        uint32_t vb = kb + 16384;

        // ---- S = Q K : m16 x n64 per warp, k=128, 1 mma per tile ----
        float S[8][4];
        #pragma unroll
        for (int nb = 0; nb < 8; nb++) { S[nb][0]=0.f; S[nb][1]=0.f; S[nb][2]=0.f; S[nb][3]=0.f; }
        #pragma unroll
        for (int kc = 0; kc < 8; kc++) {
            uint32_t a4[4];
            uint32_t ap = (uint32_t)(((kc*2 + cA) ^ l7) << 4);
            ldsm4(a4, aB + ap);
            uint32_t cp = (uint32_t)(((kc*2 + csel) ^ l7) << 4);
            #pragma unroll
            for (int nbp = 0; nbp < 4; nbp++) {
                uint32_t bk[4];
                uint32_t bo = (uint32_t)((nbp*16 + rB)*256) + cp;
                ldsm4(bk, kb + bo);
                mma16816h(S[2*nbp],   a4, bk);
                mma16816h(S[2*nbp+1], a4, bk+2);
            }
        }

        if ((j >> 1) == qt) {
            int colbase = j*64;
            #pragma unroll
            for (int nb = 0; nb < 8; nb++) {
                int c0 = colbase + nb*8 + t2;
                if (c0     == rg0) S[nb][0] = -FLTMAX;
                if (c0 + 1 == rg0) S[nb][1] = -FLTMAX;
                if (c0     == rg1) S[nb][2] = -FLTMAX;
                if (c0 + 1 == rg1) S[nb][3] = -FLTMAX;
            }
        }

        // ---- online softmax ----
        float rmax0 = -FLTMAX, rmax1 = -FLTMAX;
        #pragma unroll
        for (int nb = 0; nb < 8; nb++) {
            rmax0 = fmaxf(rmax0, fmaxf(S[nb][0], S[nb][1]));
            rmax1 = fmaxf(rmax1, fmaxf(S[nb][2], S[nb][3]));
        }
        rmax0 = fmaxf(rmax0, __shfl_xor_sync(0xffffffffu, rmax0, 1));
        rmax0 = fmaxf(rmax0, __shfl_xor_sync(0xffffffffu, rmax0, 2));
        rmax1 = fmaxf(rmax1, __shfl_xor_sync(0xffffffffu, rmax1, 1));
        rmax1 = fmaxf(rmax1, __shfl_xor_sync(0xffffffffu, rmax1, 2));
        float mn0 = fmaxf(m0, rmax0), mn1 = fmaxf(m1, rmax1);
        float cr0 = __expf(m0 - mn0), cr1 = __expf(m1 - mn1);
        m0 = mn0; m1 = mn1;
        float rs0 = 0.f, rs1 = 0.f;
        #pragma unroll
        for (int nb = 0; nb < 8; nb++) {
            S[nb][0] = __expf(S[nb][0] - mn0); rs0 += S[nb][0];
            S[nb][1] = __expf(S[nb][1] - mn0); rs0 += S[nb][1];
            S[nb][2] = __expf(S[nb][2] - mn1); rs1 += S[nb][2];
            S[nb][3] = __expf(S[nb][3] - mn1); rs1 += S[nb][3];
        }
        rs0 += __shfl_xor_sync(0xffffffffu, rs0, 1);
        rs0 += __shfl_xor_sync(0xffffffffu, rs0, 2);
        rs1 += __shfl_xor_sync(0xffffffffu, rs1, 1);
        rs1 += __shfl_xor_sync(0xffffffffu, rs1, 2);
        ls0 = ls0*cr0 + rs0;
        ls1 = ls1*cr1 + rs1;
        #pragma unroll
        for (int nb = 0; nb < 16; nb++) {
            O[nb][0] *= cr0;  O[nb][1] *= cr0;
            O[nb][2] *= cr1;  O[nb][3] *= cr1;
        }

        // ---- O += P V : P single fp16 A-frag; V single from smem ----
        #pragma unroll
        for (int kc = 0; kc < 4; kc++) {
            uint32_t ah[4];
            ah[0] = hpack2(S[2*kc][0],   S[2*kc][1]);
            ah[1] = hpack2(S[2*kc][2],   S[2*kc][3]);
            ah[2] = hpack2(S[2*kc+1][0], S[2*kc+1][1]);
            ah[3] = hpack2(S[2*kc+1][2], S[2*kc+1][3]);
            uint32_t cp = (uint32_t)(((kc*2 + csel) ^ l7) << 4);
            #pragma unroll
            for (int nbp = 0; nbp < 8; nbp++) {
                uint32_t v4[4];
                uint32_t bo = (uint32_t)((nbp*16 + rB)*128) + cp;
                ldsm4(v4, vb + bo);
                mma16816h(O[2*nbp],   ah, v4);
                mma16816h(O[2*nbp+1], ah, v4+2);
            }
        }
        __syncthreads();
    }

    // ---- epilogue: normalize, write single fp16 pre-swizzled O tiles for proj ----
    float inv0 = 1.0f / ls0, inv1 = 1.0f / ls1;
    int bb = bh >> 3, h = bh & 7;
    int rowtile = bb*8 + qt;
    int rl0 = (w << 4) + g, rl1 = rl0 + 8;
    char* ao = (char*)g_ao + (size_t)rowtile*262144;
    #pragma unroll
    for (int nb = 0; nb < 16; nb++) {
        int c16 = h*16 + nb;
        uint32_t o0 = (uint32_t)(rl0*2048 + ((c16 ^ (rl0&7))<<4) + t2*2);
        *(uint32_t*)(ao + o0) = hpack2(O[nb][0]*inv0, O[nb][1]*inv0);
        uint32_t o1 = (uint32_t)(rl1*2048 + ((c16 ^ (rl1&7))<<4) + t2*2);
        *(uint32_t*)(ao + o1) = hpack2(O[nb][2]*inv1, O[nb][3]*inv1);
    }
}

// =============================== Output projection (fp16 2-term: O single, W hi/lo) ===============================
// stage: A 16KB @0, BH 16KB @16384, BL 16KB @32768; stride 49152; 2 stages.
#define PROJ_SMEM 98304
__global__ void __launch_bounds__(256, 1) proj_mma(const float* __restrict__ bias,
                                                   float* __restrict__ out) {
    extern __shared__ char smc[];
    uint32_t sb = smem_u32(smc);
    int tid = threadIdx.x, w = tid >> 5, L = tid & 31;
    int rowtile = blockIdx.x;
    const char* ao = (const char*)g_ao + (size_t)rowtile*262144;

    int l7 = L & 7;
    int rowA = (w << 4) + ((L >> 3) & 1)*8 + l7;
    int cA = L >> 4;
    int rB = (L & 7) + ((L >> 4) & 1)*8;
    int csel = (L >> 3) & 1;
    int g = L >> 2, t2 = (L & 3)*2;

    auto prefetch = [&](int kb, int st) {
        uint32_t base = sb + st*49152;
        #pragma unroll
        for (int it = 0; it < 4; it++) {
            int e = it*256 + tid, r = e >> 3, jj = e & 7;
            uint32_t go = (uint32_t)(r*2048 + kb*128 + ((jj ^ (r&7))<<4));
            uint32_t so = (uint32_t)(r*128 + ((jj ^ (r&7))<<4));
            cpa16(base + so,          ao + go);
            cpa16(base + 16384 + so,  (const char*)g_wph + go);
            cpa16(base + 32768 + so,  (const char*)g_wpl + go);
        }
        CPA_COMMIT();
    };

    float acc[16][4];
    #pragma unroll
    for (int nb = 0; nb < 16; nb++) { acc[nb][0]=0.f; acc[nb][1]=0.f; acc[nb][2]=0.f; acc[nb][3]=0.f; }

    prefetch(0, 0);
    #pragma unroll 1
    for (int kb = 0; kb < 16; kb++) {
        if (kb < 15) { prefetch(kb + 1, (kb + 1) & 1); CPA_WAIT(1); }
        else          CPA_WAIT(0);
        __syncthreads();
        uint32_t base = sb + (kb & 1)*49152;
        uint32_t aB = base + rowA*128;
        #pragma unroll
        for (int kc = 0; kc < 4; kc++) {
            uint32_t a4[4];
            uint32_t ap = (uint32_t)(((kc*2 + cA) ^ l7) << 4);
            ldsm4(a4, aB + ap);
            uint32_t cp = (uint32_t)(((kc*2 + csel) ^ l7) << 4);
            #pragma unroll
            for (int nbp = 0; nbp < 8; nbp++) {
                uint32_t bh4[4], bl4[4];
                uint32_t bo = (uint32_t)((nbp*16 + rB)*128) + cp;
                ldsm4(bh4, base + 16384 + bo);  ldsm4(bl4, base + 32768 + bo);
                mma16816h(acc[2*nbp],   a4, bh4);    mma16816h(acc[2*nbp],   a4, bl4);
                mma16816h(acc[2*nbp+1], a4, bh4+2);  mma16816h(acc[2*nbp+1], a4, bl4+2);
            }
        }
        __syncthreads();
    }

    int r0 = rowtile*128 + (w << 4) + g, r1 = r0 + 8;
    #pragma unroll
    for (int nb = 0; nb < 16; nb++) {
        int col = nb*8 + t2;
        float b0 = bias[col], b1 = bias[col + 1];
        *(float2*)&out[r0*128 + col] = make_float2(acc[nb][0] + b0, acc[nb][1] + b1);
        *(float2*)&out[r1*128 + col] = make_float2(acc[nb][2] + b0, acc[nb][3] + b1);
    }
}

// =============================== launch ===============================
extern "C" void kernel_launch(void* const* d_in, const int* in_sizes, int n_in,
                              void* d_out, int out_size) {
    const float* x      = (const float*)d_in[0];
    const float* ln_w   = (const float*)d_in[1];
    const float* ln_b   = (const float*)d_in[2];
    const float* w_qkv  = (const float*)d_in[3];
    const float* scale  = (const float*)d_in[4];
    const float* w_proj = (const float*)d_in[5];
    const float* b_proj = (const float*)d_in[6];
    float* out = (float*)d_out;

    cudaFuncSetAttribute(qkv_mma,  cudaFuncAttributeMaxDynamicSharedMemorySize, QKV_SMEM);
    cudaFuncSetAttribute(attn_mma, cudaFuncAttributeMaxDynamicSharedMemorySize, SMEM_ATTN);
    cudaFuncSetAttribute(proj_mma, cudaFuncAttributeMaxDynamicSharedMemorySize, PROJ_SMEM);

    prep_wqkv<<<768, 256>>>(w_qkv);
    prep_wp  <<<256, 256>>>(w_proj);
    ln_kernel<<<2048, 256>>>(x, ln_w, ln_b);
    qkv_mma  <<<dim3(48, 128), 256, QKV_SMEM>>>(scale);
    attn_mma <<<dim3(8, 128), 256, SMEM_ATTN>>>();
    proj_mma <<<128, 256, PROJ_SMEM>>>(b_proj, out);
}